// round 1
// baseline (speedup 1.0000x reference)
#include <cuda_runtime.h>

// Problem constants
#define BB  4
#define SS  2048
#define DD  1024
#define HH  16
#define HDD 64
#define PFF 4096
#define NR  (BB * SS)   // 8192 rows

// ---------------------------------------------------------------------------
// Scratch (static __device__ — no allocation allowed)
// ---------------------------------------------------------------------------
__device__ float g_q[BB * HH * SS * HDD];     // 32 MB, [b][h][s][d]
__device__ float g_k[BB * HH * SS * HDD];     // 32 MB
__device__ float g_v[BB * HH * SS * HDD];     // 32 MB
__device__ float g_attn[NR * DD];             // 32 MB, [n][d]
__device__ float g_tmp[NR * DD];              // 32 MB
__device__ float g_src1[NR * DD];             // 32 MB
__device__ float g_ff1[NR * PFF];             // 128 MB

// ---------------------------------------------------------------------------
// SGEMM: C[M,N] = A[M,K] @ W[K,N] + bias, optional ReLU, optional BHSD output
// 128x128 block tile, BK=8, 256 threads, 8x8 per thread, double-buffered smem.
// ---------------------------------------------------------------------------
template <bool RELU, bool BHSD>
__global__ __launch_bounds__(256, 2)
void sgemm_kernel(const float* __restrict__ A, const float* __restrict__ Wt,
                  const float* __restrict__ bias, float* __restrict__ C,
                  int M, int N, int K)
{
    __shared__ float As[2][8][128];
    __shared__ float Bs[2][8][128];

    const int tid = threadIdx.x;
    const int bm  = blockIdx.y * 128;
    const int bn  = blockIdx.x * 128;
    const int tx  = tid & 15;
    const int ty  = tid >> 4;

    const int a_row = tid >> 1;          // 0..127
    const int a_k   = (tid & 1) * 4;     // 0 or 4
    const int b_row = tid >> 5;          // 0..7
    const int b_col = (tid & 31) * 4;    // 0..124

    const float* Ap = A + (size_t)(bm + a_row) * K + a_k;
    const float* Bp = Wt + (size_t)b_row * N + bn + b_col;

    float4 a_ld = *(const float4*)Ap;
    float4 b_ld = *(const float4*)Bp;
    As[0][a_k + 0][a_row] = a_ld.x;
    As[0][a_k + 1][a_row] = a_ld.y;
    As[0][a_k + 2][a_row] = a_ld.z;
    As[0][a_k + 3][a_row] = a_ld.w;
    *(float4*)&Bs[0][b_row][b_col] = b_ld;
    __syncthreads();

    float acc[8][8];
#pragma unroll
    for (int i = 0; i < 8; i++)
#pragma unroll
        for (int j = 0; j < 8; j++) acc[i][j] = 0.0f;

    const int nk = K >> 3;
    int buf = 0;
    for (int t = 0; t < nk; ++t) {
        if (t + 1 < nk) {
            a_ld = *(const float4*)(Ap + (t + 1) * 8);
            b_ld = *(const float4*)(Bp + (size_t)(t + 1) * 8 * N);
        }
#pragma unroll
        for (int kk = 0; kk < 8; ++kk) {
            float4 a0 = *(const float4*)&As[buf][kk][ty * 8];
            float4 a1 = *(const float4*)&As[buf][kk][ty * 8 + 4];
            float4 b0 = *(const float4*)&Bs[buf][kk][tx * 8];
            float4 b1 = *(const float4*)&Bs[buf][kk][tx * 8 + 4];
            float ar[8] = {a0.x, a0.y, a0.z, a0.w, a1.x, a1.y, a1.z, a1.w};
            float br[8] = {b0.x, b0.y, b0.z, b0.w, b1.x, b1.y, b1.z, b1.w};
#pragma unroll
            for (int i = 0; i < 8; i++)
#pragma unroll
                for (int j = 0; j < 8; j++)
                    acc[i][j] += ar[i] * br[j];
        }
        if (t + 1 < nk) {
            int nb = buf ^ 1;
            As[nb][a_k + 0][a_row] = a_ld.x;
            As[nb][a_k + 1][a_row] = a_ld.y;
            As[nb][a_k + 2][a_row] = a_ld.z;
            As[nb][a_k + 3][a_row] = a_ld.w;
            *(float4*)&Bs[nb][b_row][b_col] = b_ld;
        }
        __syncthreads();
        buf ^= 1;
    }

    const int row0 = bm + ty * 8;
    const int col0 = bn + tx * 8;
    float bv[8];
#pragma unroll
    for (int j = 0; j < 8; j++) bv[j] = bias[col0 + j];

#pragma unroll
    for (int i = 0; i < 8; i++) {
        const int m = row0 + i;
        float o[8];
#pragma unroll
        for (int j = 0; j < 8; j++) {
            float v2 = acc[i][j] + bv[j];
            o[j] = RELU ? fmaxf(v2, 0.0f) : v2;
        }
        float* dst;
        if (BHSD) {
            // m = b*S + s ; col = h*64 + d  ->  [(b*H+h)*S + s]*64 + d
            int b_  = m >> 11;          // /2048
            int s_  = m & 2047;
            int h_  = col0 >> 6;
            int d0  = col0 & 63;
            dst = C + ((size_t)(b_ * HH + h_) * SS + s_) * HDD + d0;
        } else {
            dst = C + (size_t)m * N + col0;
        }
        *(float4*)dst       = make_float4(o[0], o[1], o[2], o[3]);
        *(float4*)(dst + 4) = make_float4(o[4], o[5], o[6], o[7]);
    }
}

// ---------------------------------------------------------------------------
// Flash attention: per block 64 queries of one (b,h); loops over 64-key tiles.
// 256 threads as (16 tx, 16 ty); each thread owns a 4(row)x4(col) micro-tile.
// Q pre-scaled by 1/sqrt(HD). K stored d-major for conflict-free float4 reads.
// ---------------------------------------------------------------------------
__global__ __launch_bounds__(256)
void flash_kernel(const float* __restrict__ Q, const float* __restrict__ Kg,
                  const float* __restrict__ Vg, float* __restrict__ Og)
{
    extern __shared__ float sm[];
    float* Qs  = sm;                // [64][64]   q-major
    float* Kts = Qs + 64 * 64;      // [64][68]   d-major (transposed)
    float* Vs  = Kts + 64 * 68;     // [64][68]   c-major
    float* Ps  = Vs + 64 * 68;      // [64][68]   r-major

    const int tid = threadIdx.x;
    const int tx  = tid & 15;
    const int ty  = tid >> 4;
    const int bh  = blockIdx.y;
    const int q0  = blockIdx.x * 64;

    const float* qb = Q + (size_t)bh * SS * HDD + (size_t)q0 * HDD;
    const float* kb = Kg + (size_t)bh * SS * HDD;
    const float* vb = Vg + (size_t)bh * SS * HDD;

    // Load + pre-scale Q tile
    for (int i = tid; i < 64 * 16; i += 256) {
        float4 t4 = ((const float4*)qb)[i];
        t4.x *= 0.125f; t4.y *= 0.125f; t4.z *= 0.125f; t4.w *= 0.125f;
        ((float4*)Qs)[i] = t4;
    }

    float m_i[4], l_i[4], acc[4][4];
#pragma unroll
    for (int i = 0; i < 4; i++) {
        m_i[i] = -3.0e38f;
        l_i[i] = 0.0f;
#pragma unroll
        for (int j = 0; j < 4; j++) acc[i][j] = 0.0f;
    }

    for (int kt = 0; kt < SS / 64; ++kt) {
        __syncthreads();   // prev-iter readers of Kts/Vs/Ps done
        const float4* kp = (const float4*)(kb + (size_t)kt * 64 * HDD);
        const float4* vp = (const float4*)(vb + (size_t)kt * 64 * HDD);
        for (int idx = tid; idx < 64 * 16; idx += 256) {
            int row = idx >> 4;
            int d4  = (idx & 15) << 2;
            float4 kv = kp[idx];
            Kts[(d4 + 0) * 68 + row] = kv.x;
            Kts[(d4 + 1) * 68 + row] = kv.y;
            Kts[(d4 + 2) * 68 + row] = kv.z;
            Kts[(d4 + 3) * 68 + row] = kv.w;
            *(float4*)&Vs[row * 68 + d4] = vp[idx];
        }
        __syncthreads();

        // scores: s[i][j] = sum_d Qs[r_i][d] * K[c_j][d]   (Q pre-scaled)
        float s0[4][4];
#pragma unroll
        for (int i = 0; i < 4; i++)
#pragma unroll
            for (int j = 0; j < 4; j++) s0[i][j] = 0.0f;

        for (int d = 0; d < 64; ++d) {
            float4 kk = *(const float4*)&Kts[d * 68 + tx * 4];
#pragma unroll
            for (int i = 0; i < 4; i++) {
                float qv = Qs[(ty * 4 + i) * 64 + d];
                s0[i][0] += qv * kk.x;
                s0[i][1] += qv * kk.y;
                s0[i][2] += qv * kk.z;
                s0[i][3] += qv * kk.w;
            }
        }

        // online softmax (rows shared by the 16 threads of same ty)
#pragma unroll
        for (int i = 0; i < 4; i++) {
            float mx = fmaxf(fmaxf(s0[i][0], s0[i][1]), fmaxf(s0[i][2], s0[i][3]));
            mx = fmaxf(mx, __shfl_xor_sync(0xffffffffu, mx, 1));
            mx = fmaxf(mx, __shfl_xor_sync(0xffffffffu, mx, 2));
            mx = fmaxf(mx, __shfl_xor_sync(0xffffffffu, mx, 4));
            mx = fmaxf(mx, __shfl_xor_sync(0xffffffffu, mx, 8));
            float mnew  = fmaxf(m_i[i], mx);
            float alpha = __expf(m_i[i] - mnew);
            m_i[i] = mnew;
            float rs = 0.0f;
#pragma unroll
            for (int j = 0; j < 4; j++) {
                s0[i][j] = __expf(s0[i][j] - mnew);
                rs += s0[i][j];
            }
            rs += __shfl_xor_sync(0xffffffffu, rs, 1);
            rs += __shfl_xor_sync(0xffffffffu, rs, 2);
            rs += __shfl_xor_sync(0xffffffffu, rs, 4);
            rs += __shfl_xor_sync(0xffffffffu, rs, 8);
            l_i[i] = l_i[i] * alpha + rs;
#pragma unroll
            for (int j = 0; j < 4; j++) acc[i][j] *= alpha;
            *(float4*)&Ps[(ty * 4 + i) * 68 + tx * 4] =
                make_float4(s0[i][0], s0[i][1], s0[i][2], s0[i][3]);
        }
        __syncthreads();

        // acc += P @ V
        for (int c = 0; c < 64; ++c) {
            float4 vv = *(const float4*)&Vs[c * 68 + tx * 4];
#pragma unroll
            for (int i = 0; i < 4; i++) {
                float p = Ps[(ty * 4 + i) * 68 + c];
                acc[i][0] += p * vv.x;
                acc[i][1] += p * vv.y;
                acc[i][2] += p * vv.z;
                acc[i][3] += p * vv.w;
            }
        }
    }

    // write out in [B,S,D] layout: row n = b*S + q, col = h*64 + hd
    const int b_ = bh >> 4;
    const int h_ = bh & 15;
#pragma unroll
    for (int i = 0; i < 4; i++) {
        int r = ty * 4 + i;
        float inv = 1.0f / l_i[i];
        size_t n = (size_t)b_ * SS + q0 + r;
        float4 o = make_float4(acc[i][0] * inv, acc[i][1] * inv,
                               acc[i][2] * inv, acc[i][3] * inv);
        *(float4*)(Og + n * DD + h_ * HDD + tx * 4) = o;
    }
}

// ---------------------------------------------------------------------------
// Fused residual + LayerNorm: out = LN(x1 + x2) * gamma + beta, D=1024 per row
// 256 threads/row, 1 float4 per thread.
// ---------------------------------------------------------------------------
__global__ __launch_bounds__(256)
void ln_kernel(const float* __restrict__ x1, const float* __restrict__ x2,
               const float* __restrict__ gamma, const float* __restrict__ beta,
               float* __restrict__ out)
{
    const int row = blockIdx.x;
    const int tid = threadIdx.x;
    const float4 a = ((const float4*)(x1 + (size_t)row * DD))[tid];
    const float4 b = ((const float4*)(x2 + (size_t)row * DD))[tid];
    float4 x = make_float4(a.x + b.x, a.y + b.y, a.z + b.z, a.w + b.w);

    float s = x.x + x.y + x.z + x.w;
    float q = x.x * x.x + x.y * x.y + x.z * x.z + x.w * x.w;

    __shared__ float shs[8], shq[8];
    const int lane = tid & 31, wid = tid >> 5;
#pragma unroll
    for (int o = 16; o; o >>= 1) {
        s += __shfl_xor_sync(0xffffffffu, s, o);
        q += __shfl_xor_sync(0xffffffffu, q, o);
    }
    if (lane == 0) { shs[wid] = s; shq[wid] = q; }
    __syncthreads();
    if (tid == 0) {
        float ts = 0.0f, tq = 0.0f;
#pragma unroll
        for (int i = 0; i < 8; i++) { ts += shs[i]; tq += shq[i]; }
        shs[0] = ts; shq[0] = tq;
    }
    __syncthreads();
    const float mean = shs[0] * (1.0f / DD);
    const float var  = shq[0] * (1.0f / DD) - mean * mean;
    const float rstd = rsqrtf(var + 1e-5f);

    const float4 g = ((const float4*)gamma)[tid];
    const float4 be = ((const float4*)beta)[tid];
    float4 o;
    o.x = (x.x - mean) * rstd * g.x + be.x;
    o.y = (x.y - mean) * rstd * g.y + be.y;
    o.z = (x.z - mean) * rstd * g.z + be.z;
    o.w = (x.w - mean) * rstd * g.w + be.w;
    ((float4*)(out + (size_t)row * DD))[tid] = o;
}

// ---------------------------------------------------------------------------
// Launch
// ---------------------------------------------------------------------------
extern "C" void kernel_launch(void* const* d_in, const int* in_sizes, int n_in,
                              void* d_out, int out_size)
{
    const float* src = (const float*)d_in[0];
    const float* Wq  = (const float*)d_in[1];
    const float* bq  = (const float*)d_in[2];
    const float* Wk  = (const float*)d_in[3];
    const float* bk  = (const float*)d_in[4];
    const float* Wv  = (const float*)d_in[5];
    const float* bv  = (const float*)d_in[6];
    const float* Wo  = (const float*)d_in[7];
    const float* bo  = (const float*)d_in[8];
    const float* g1  = (const float*)d_in[9];
    const float* b1  = (const float*)d_in[10];
    const float* W1  = (const float*)d_in[11];
    const float* bf1 = (const float*)d_in[12];
    const float* W2  = (const float*)d_in[13];
    const float* bf2 = (const float*)d_in[14];
    const float* g2  = (const float*)d_in[15];
    const float* b2  = (const float*)d_in[16];
    float* out = (float*)d_out;

    float *qp, *kp, *vp, *attnp, *tmpp, *src1p, *ff1p;
    cudaGetSymbolAddress((void**)&qp,    g_q);
    cudaGetSymbolAddress((void**)&kp,    g_k);
    cudaGetSymbolAddress((void**)&vp,    g_v);
    cudaGetSymbolAddress((void**)&attnp, g_attn);
    cudaGetSymbolAddress((void**)&tmpp,  g_tmp);
    cudaGetSymbolAddress((void**)&src1p, g_src1);
    cudaGetSymbolAddress((void**)&ff1p,  g_ff1);

    const int FLASH_SMEM = (64 * 64 + 3 * 64 * 68) * 4;   // 68608 B
    cudaFuncSetAttribute(flash_kernel,
                         cudaFuncAttributeMaxDynamicSharedMemorySize, FLASH_SMEM);

    dim3 blk(256);
    dim3 gD(DD / 128, NR / 128);     // (8, 64)
    dim3 gPF(PFF / 128, NR / 128);   // (32, 64)
    dim3 gF(SS / 64, BB * HH);       // (32, 64)

    // QKV projections -> [B,H,S,HD]
    sgemm_kernel<false, true><<<gD, blk>>>(src, Wq, bq, qp, NR, DD, DD);
    sgemm_kernel<false, true><<<gD, blk>>>(src, Wk, bk, kp, NR, DD, DD);
    sgemm_kernel<false, true><<<gD, blk>>>(src, Wv, bv, vp, NR, DD, DD);
    // attention
    flash_kernel<<<gF, blk, FLASH_SMEM>>>(qp, kp, vp, attnp);
    // O projection
    sgemm_kernel<false, false><<<gD, blk>>>(attnp, Wo, bo, tmpp, NR, DD, DD);
    // residual + LN 1
    ln_kernel<<<NR, blk>>>(src, tmpp, g1, b1, src1p);
    // FFN
    sgemm_kernel<true, false><<<gPF, blk>>>(src1p, W1, bf1, ff1p, NR, PFF, DD);
    sgemm_kernel<false, false><<<gD, blk>>>(ff1p, W2, bf2, tmpp, NR, DD, PFF);
    // residual + LN 2 -> output
    ln_kernel<<<NR, blk>>>(src1p, tmpp, g2, b2, out);
}

// round 3
// speedup vs baseline: 1.5693x; 1.5693x over previous
#include <cuda_runtime.h>
#include <cstdint>

// Problem constants
#define BB  4
#define SS  2048
#define DD  1024
#define HH  16
#define HDD 64
#define PFF 4096
#define NR  (BB * SS)   // 8192 rows

// ---------------------------------------------------------------------------
// Scratch (static __device__ — no allocation allowed)
// ---------------------------------------------------------------------------
__device__ float g_q[BB * HH * SS * HDD];     // 32 MB, [b][h][s][d]
__device__ float g_k[BB * HH * SS * HDD];     // 32 MB
__device__ float g_v[BB * HH * SS * HDD];     // 32 MB
__device__ float g_attn[NR * DD];             // 32 MB
__device__ float g_tmp[NR * DD];              // 32 MB
__device__ float g_src1[NR * DD];             // 32 MB
__device__ float g_ff1[NR * PFF];             // 128 MB

// ---------------------------------------------------------------------------
// TF32 tensor-core GEMM: C[M,N] = A[M,K] @ W[K,N] + bias (+ReLU) (+BHSD remap)
// Block tile 128x128, BK=32, 256 threads = 8 warps (2x4), warp tile 64x32.
// mma.sync.m16n8k8 tf32, cp.async double-buffered smem.
// ---------------------------------------------------------------------------
#define BM 128
#define BN 128
#define BK 32
#define ASTRIDE 36    // floats per A smem row (pad: bank-conflict-free frags)
#define BSTRIDE 132   // floats per B smem row
#define ASZ (BM * ASTRIDE)   // 4608 floats
#define BSZ (BK * BSTRIDE)   // 4224 floats
#define SMEM_FLOATS (2 * (ASZ + BSZ))

__device__ __forceinline__ uint32_t f2tf32(float x) {
    uint32_t y;
    asm("cvt.rna.tf32.f32 %0, %1;" : "=r"(y) : "f"(x));
    return y;
}

__device__ __forceinline__ void cp16(uint32_t dst_smem, const void* src) {
    asm volatile("cp.async.cg.shared.global [%0], [%1], 16;\n" ::
                 "r"(dst_smem), "l"(src));
}

__device__ __forceinline__ void mma_tf32(float& c0, float& c1, float& c2, float& c3,
                                         uint32_t a0, uint32_t a1, uint32_t a2, uint32_t a3,
                                         uint32_t b0, uint32_t b1) {
    asm volatile(
        "mma.sync.aligned.m16n8k8.row.col.f32.tf32.tf32.f32 "
        "{%0,%1,%2,%3}, {%4,%5,%6,%7}, {%8,%9}, {%0,%1,%2,%3};\n"
        : "+f"(c0), "+f"(c1), "+f"(c2), "+f"(c3)
        : "r"(a0), "r"(a1), "r"(a2), "r"(a3), "r"(b0), "r"(b1));
}

template <bool RELU, bool BHSD>
__global__ __launch_bounds__(256)
void mma_gemm_kernel(const float* __restrict__ A, const float* __restrict__ W,
                     const float* __restrict__ bias, float* __restrict__ C,
                     int M, int N, int K)
{
    extern __shared__ float sm[];
    float* sA[2] = { sm, sm + ASZ };
    float* sB[2] = { sm + 2 * ASZ, sm + 2 * ASZ + BSZ };

    const int tid  = threadIdx.x;
    const int lane = tid & 31;
    const int warp = tid >> 5;
    const int wm   = warp >> 2;   // 0..1
    const int wn   = warp & 3;    // 0..3
    const int bm   = blockIdx.y * BM;
    const int bn   = blockIdx.x * BN;

    // global->smem mapping
    const int a_row = tid >> 3;          // 0..31 (+32/pass, 4 passes)
    const int a_col = (tid & 7) * 4;     // 0..28
    const int b_row = tid >> 5;          // 0..7 (+8/pass, 4 passes)
    const int b_col = (tid & 31) * 4;    // 0..124

    const float* Ag = A + (size_t)(bm + a_row) * K + a_col;
    const float* Bg = W + (size_t)b_row * N + bn + b_col;

    uint32_t sA_dst[2], sB_dst[2];
    sA_dst[0] = (uint32_t)__cvta_generic_to_shared(sA[0] + a_row * ASTRIDE + a_col);
    sA_dst[1] = (uint32_t)__cvta_generic_to_shared(sA[1] + a_row * ASTRIDE + a_col);
    sB_dst[0] = (uint32_t)__cvta_generic_to_shared(sB[0] + b_row * BSTRIDE + b_col);
    sB_dst[1] = (uint32_t)__cvta_generic_to_shared(sB[1] + b_row * BSTRIDE + b_col);

    const int nk = K / BK;

    // prologue: tile 0 into buf 0
    {
#pragma unroll
        for (int p = 0; p < 4; p++)
            cp16(sA_dst[0] + p * 32 * ASTRIDE * 4, Ag + (size_t)p * 32 * K);
#pragma unroll
        for (int p = 0; p < 4; p++)
            cp16(sB_dst[0] + p * 8 * BSTRIDE * 4, Bg + (size_t)p * 8 * N);
        asm volatile("cp.async.commit_group;\n" ::);
    }

    float acc[4][4][4];
#pragma unroll
    for (int i = 0; i < 4; i++)
#pragma unroll
        for (int j = 0; j < 4; j++)
#pragma unroll
            for (int r = 0; r < 4; r++) acc[i][j][r] = 0.0f;

    const int lr = lane >> 2;   // 0..7
    const int lc = lane & 3;    // 0..3

    int buf = 0;
    for (int t = 0; t < nk; ++t) {
        asm volatile("cp.async.wait_group 0;\n" ::);
        __syncthreads();

        if (t + 1 < nk) {
            const float* Agn = Ag + (size_t)(t + 1) * BK;
            const float* Bgn = Bg + (size_t)(t + 1) * BK * N;
            const int nb = buf ^ 1;
#pragma unroll
            for (int p = 0; p < 4; p++)
                cp16(sA_dst[nb] + p * 32 * ASTRIDE * 4, Agn + (size_t)p * 32 * K);
#pragma unroll
            for (int p = 0; p < 4; p++)
                cp16(sB_dst[nb] + p * 8 * BSTRIDE * 4, Bgn + (size_t)p * 8 * N);
            asm volatile("cp.async.commit_group;\n" ::);
        }

        const float* __restrict__ sAb = sA[buf];
        const float* __restrict__ sBb = sB[buf];

#pragma unroll
        for (int kk = 0; kk < 4; ++kk) {
            const int k0 = kk * 8 + lc;
            uint32_t af[4][4];
#pragma unroll
            for (int mt = 0; mt < 4; mt++) {
                const int r0 = wm * 64 + mt * 16 + lr;
                af[mt][0] = f2tf32(sAb[r0 * ASTRIDE + k0]);
                af[mt][1] = f2tf32(sAb[(r0 + 8) * ASTRIDE + k0]);
                af[mt][2] = f2tf32(sAb[r0 * ASTRIDE + k0 + 4]);
                af[mt][3] = f2tf32(sAb[(r0 + 8) * ASTRIDE + k0 + 4]);
            }
            uint32_t bf[4][2];
#pragma unroll
            for (int nt = 0; nt < 4; nt++) {
                const int c0 = wn * 32 + nt * 8 + lr;
                bf[nt][0] = f2tf32(sBb[(kk * 8 + lc) * BSTRIDE + c0]);
                bf[nt][1] = f2tf32(sBb[(kk * 8 + 4 + lc) * BSTRIDE + c0]);
            }
#pragma unroll
            for (int mt = 0; mt < 4; mt++)
#pragma unroll
                for (int nt = 0; nt < 4; nt++)
                    mma_tf32(acc[mt][nt][0], acc[mt][nt][1],
                             acc[mt][nt][2], acc[mt][nt][3],
                             af[mt][0], af[mt][1], af[mt][2], af[mt][3],
                             bf[nt][0], bf[nt][1]);
        }
        buf ^= 1;
    }

    // epilogue
#pragma unroll
    for (int mt = 0; mt < 4; mt++) {
#pragma unroll
        for (int nt = 0; nt < 4; nt++) {
            const int col = bn + wn * 32 + nt * 8 + lc * 2;
            const float bv0 = bias[col];
            const float bv1 = bias[col + 1];
#pragma unroll
            for (int half = 0; half < 2; half++) {
                const int row = bm + wm * 64 + mt * 16 + lr + half * 8;
                float v0 = acc[mt][nt][half * 2 + 0] + bv0;
                float v1 = acc[mt][nt][half * 2 + 1] + bv1;
                if (RELU) { v0 = fmaxf(v0, 0.0f); v1 = fmaxf(v1, 0.0f); }
                float* dst;
                if (BHSD) {
                    const int b_ = row >> 11;
                    const int s_ = row & 2047;
                    const int h_ = col >> 6;
                    const int d_ = col & 63;
                    dst = C + ((size_t)(b_ * HH + h_) * SS + s_) * HDD + d_;
                } else {
                    dst = C + (size_t)row * N + col;
                }
                *(float2*)dst = make_float2(v0, v1);
            }
        }
    }
}

// ---------------------------------------------------------------------------
// Flash attention (fp32)
// ---------------------------------------------------------------------------
__global__ __launch_bounds__(256)
void flash_kernel(const float* __restrict__ Q, const float* __restrict__ Kg,
                  const float* __restrict__ Vg, float* __restrict__ Og)
{
    extern __shared__ float sm[];
    float* Qs  = sm;                // [64][64]
    float* Kts = Qs + 64 * 64;      // [64][68] d-major
    float* Vs  = Kts + 64 * 68;     // [64][68]
    float* Ps  = Vs + 64 * 68;      // [64][68]

    const int tid = threadIdx.x;
    const int tx  = tid & 15;
    const int ty  = tid >> 4;
    const int bh  = blockIdx.y;
    const int q0  = blockIdx.x * 64;

    const float* qb = Q + (size_t)bh * SS * HDD + (size_t)q0 * HDD;
    const float* kb = Kg + (size_t)bh * SS * HDD;
    const float* vb = Vg + (size_t)bh * SS * HDD;

    for (int i = tid; i < 64 * 16; i += 256) {
        float4 t4 = ((const float4*)qb)[i];
        t4.x *= 0.125f; t4.y *= 0.125f; t4.z *= 0.125f; t4.w *= 0.125f;
        ((float4*)Qs)[i] = t4;
    }

    float m_i[4], l_i[4], acc[4][4];
#pragma unroll
    for (int i = 0; i < 4; i++) {
        m_i[i] = -3.0e38f;
        l_i[i] = 0.0f;
#pragma unroll
        for (int j = 0; j < 4; j++) acc[i][j] = 0.0f;
    }

    for (int kt = 0; kt < SS / 64; ++kt) {
        __syncthreads();
        const float4* kp = (const float4*)(kb + (size_t)kt * 64 * HDD);
        const float4* vp = (const float4*)(vb + (size_t)kt * 64 * HDD);
        for (int idx = tid; idx < 64 * 16; idx += 256) {
            int row = idx >> 4;
            int d4  = (idx & 15) << 2;
            float4 kv = kp[idx];
            Kts[(d4 + 0) * 68 + row] = kv.x;
            Kts[(d4 + 1) * 68 + row] = kv.y;
            Kts[(d4 + 2) * 68 + row] = kv.z;
            Kts[(d4 + 3) * 68 + row] = kv.w;
            *(float4*)&Vs[row * 68 + d4] = vp[idx];
        }
        __syncthreads();

        float s0[4][4];
#pragma unroll
        for (int i = 0; i < 4; i++)
#pragma unroll
            for (int j = 0; j < 4; j++) s0[i][j] = 0.0f;

        for (int d = 0; d < 64; ++d) {
            float4 kk = *(const float4*)&Kts[d * 68 + tx * 4];
#pragma unroll
            for (int i = 0; i < 4; i++) {
                float qv = Qs[(ty * 4 + i) * 64 + d];
                s0[i][0] += qv * kk.x;
                s0[i][1] += qv * kk.y;
                s0[i][2] += qv * kk.z;
                s0[i][3] += qv * kk.w;
            }
        }

#pragma unroll
        for (int i = 0; i < 4; i++) {
            float mx = fmaxf(fmaxf(s0[i][0], s0[i][1]), fmaxf(s0[i][2], s0[i][3]));
            mx = fmaxf(mx, __shfl_xor_sync(0xffffffffu, mx, 1));
            mx = fmaxf(mx, __shfl_xor_sync(0xffffffffu, mx, 2));
            mx = fmaxf(mx, __shfl_xor_sync(0xffffffffu, mx, 4));
            mx = fmaxf(mx, __shfl_xor_sync(0xffffffffu, mx, 8));
            float mnew  = fmaxf(m_i[i], mx);
            float alpha = __expf(m_i[i] - mnew);
            m_i[i] = mnew;
            float rs = 0.0f;
#pragma unroll
            for (int j = 0; j < 4; j++) {
                s0[i][j] = __expf(s0[i][j] - mnew);
                rs += s0[i][j];
            }
            rs += __shfl_xor_sync(0xffffffffu, rs, 1);
            rs += __shfl_xor_sync(0xffffffffu, rs, 2);
            rs += __shfl_xor_sync(0xffffffffu, rs, 4);
            rs += __shfl_xor_sync(0xffffffffu, rs, 8);
            l_i[i] = l_i[i] * alpha + rs;
#pragma unroll
            for (int j = 0; j < 4; j++) acc[i][j] *= alpha;
            *(float4*)&Ps[(ty * 4 + i) * 68 + tx * 4] =
                make_float4(s0[i][0], s0[i][1], s0[i][2], s0[i][3]);
        }
        __syncthreads();

        for (int c = 0; c < 64; ++c) {
            float4 vv = *(const float4*)&Vs[c * 68 + tx * 4];
#pragma unroll
            for (int i = 0; i < 4; i++) {
                float p = Ps[(ty * 4 + i) * 68 + c];
                acc[i][0] += p * vv.x;
                acc[i][1] += p * vv.y;
                acc[i][2] += p * vv.z;
                acc[i][3] += p * vv.w;
            }
        }
    }

    const int b_ = bh >> 4;
    const int h_ = bh & 15;
#pragma unroll
    for (int i = 0; i < 4; i++) {
        int r = ty * 4 + i;
        float inv = 1.0f / l_i[i];
        size_t n = (size_t)b_ * SS + q0 + r;
        float4 o = make_float4(acc[i][0] * inv, acc[i][1] * inv,
                               acc[i][2] * inv, acc[i][3] * inv);
        *(float4*)(Og + n * DD + h_ * HDD + tx * 4) = o;
    }
}

// ---------------------------------------------------------------------------
// Fused residual + LayerNorm
// ---------------------------------------------------------------------------
__global__ __launch_bounds__(256)
void ln_kernel(const float* __restrict__ x1, const float* __restrict__ x2,
               const float* __restrict__ gamma, const float* __restrict__ beta,
               float* __restrict__ out)
{
    const int row = blockIdx.x;
    const int tid = threadIdx.x;
    const float4 a = ((const float4*)(x1 + (size_t)row * DD))[tid];
    const float4 b = ((const float4*)(x2 + (size_t)row * DD))[tid];
    float4 x = make_float4(a.x + b.x, a.y + b.y, a.z + b.z, a.w + b.w);

    float s = x.x + x.y + x.z + x.w;
    float q = x.x * x.x + x.y * x.y + x.z * x.z + x.w * x.w;

    __shared__ float shs[8], shq[8];
    const int lane = tid & 31, wid = tid >> 5;
#pragma unroll
    for (int o = 16; o; o >>= 1) {
        s += __shfl_xor_sync(0xffffffffu, s, o);
        q += __shfl_xor_sync(0xffffffffu, q, o);
    }
    if (lane == 0) { shs[wid] = s; shq[wid] = q; }
    __syncthreads();
    if (tid == 0) {
        float ts = 0.0f, tq = 0.0f;
#pragma unroll
        for (int i = 0; i < 8; i++) { ts += shs[i]; tq += shq[i]; }
        shs[0] = ts; shq[0] = tq;
    }
    __syncthreads();
    const float mean = shs[0] * (1.0f / DD);
    const float var  = shq[0] * (1.0f / DD) - mean * mean;
    const float rstd = rsqrtf(var + 1e-5f);

    const float4 g  = ((const float4*)gamma)[tid];
    const float4 be = ((const float4*)beta)[tid];
    float4 o;
    o.x = (x.x - mean) * rstd * g.x + be.x;
    o.y = (x.y - mean) * rstd * g.y + be.y;
    o.z = (x.z - mean) * rstd * g.z + be.z;
    o.w = (x.w - mean) * rstd * g.w + be.w;
    ((float4*)(out + (size_t)row * DD))[tid] = o;
}

// ---------------------------------------------------------------------------
// Launch
// ---------------------------------------------------------------------------
extern "C" void kernel_launch(void* const* d_in, const int* in_sizes, int n_in,
                              void* d_out, int out_size)
{
    const float* src = (const float*)d_in[0];
    const float* Wq  = (const float*)d_in[1];
    const float* bq  = (const float*)d_in[2];
    const float* Wk  = (const float*)d_in[3];
    const float* bk  = (const float*)d_in[4];
    const float* Wv  = (const float*)d_in[5];
    const float* bv  = (const float*)d_in[6];
    const float* Wo  = (const float*)d_in[7];
    const float* bo  = (const float*)d_in[8];
    const float* g1  = (const float*)d_in[9];
    const float* b1  = (const float*)d_in[10];
    const float* W1  = (const float*)d_in[11];
    const float* bf1 = (const float*)d_in[12];
    const float* W2  = (const float*)d_in[13];
    const float* bf2 = (const float*)d_in[14];
    const float* g2  = (const float*)d_in[15];
    const float* b2  = (const float*)d_in[16];
    float* out = (float*)d_out;

    float *qp, *kp, *vp, *attnp, *tmpp, *src1p, *ff1p;
    cudaGetSymbolAddress((void**)&qp,    g_q);
    cudaGetSymbolAddress((void**)&kp,    g_k);
    cudaGetSymbolAddress((void**)&vp,    g_v);
    cudaGetSymbolAddress((void**)&attnp, g_attn);
    cudaGetSymbolAddress((void**)&tmpp,  g_tmp);
    cudaGetSymbolAddress((void**)&src1p, g_src1);
    cudaGetSymbolAddress((void**)&ff1p,  g_ff1);

    const int GEMM_SMEM = SMEM_FLOATS * 4;                // 70656 B
    const int FLASH_SMEM = (64 * 64 + 3 * 64 * 68) * 4;   // 68608 B

    cudaFuncSetAttribute(mma_gemm_kernel<false, true>,
                         cudaFuncAttributeMaxDynamicSharedMemorySize, GEMM_SMEM);
    cudaFuncSetAttribute(mma_gemm_kernel<false, false>,
                         cudaFuncAttributeMaxDynamicSharedMemorySize, GEMM_SMEM);
    cudaFuncSetAttribute(mma_gemm_kernel<true, false>,
                         cudaFuncAttributeMaxDynamicSharedMemorySize, GEMM_SMEM);
    cudaFuncSetAttribute(flash_kernel,
                         cudaFuncAttributeMaxDynamicSharedMemorySize, FLASH_SMEM);

    dim3 blk(256);
    dim3 gD(DD / BN, NR / BM);     // (8, 64)
    dim3 gPF(PFF / BN, NR / BM);   // (32, 64)
    dim3 gF(SS / 64, BB * HH);     // (32, 64)

    // QKV projections -> [B,H,S,HD]
    mma_gemm_kernel<false, true><<<gD, blk, GEMM_SMEM>>>(src, Wq, bq, qp, NR, DD, DD);
    mma_gemm_kernel<false, true><<<gD, blk, GEMM_SMEM>>>(src, Wk, bk, kp, NR, DD, DD);
    mma_gemm_kernel<false, true><<<gD, blk, GEMM_SMEM>>>(src, Wv, bv, vp, NR, DD, DD);
    // attention
    flash_kernel<<<gF, blk, FLASH_SMEM>>>(qp, kp, vp, attnp);
    // O projection
    mma_gemm_kernel<false, false><<<gD, blk, GEMM_SMEM>>>(attnp, Wo, bo, tmpp, NR, DD, DD);
    // residual + LN 1
    ln_kernel<<<NR, blk>>>(src, tmpp, g1, b1, src1p);
    // FFN
    mma_gemm_kernel<true, false><<<gPF, blk, GEMM_SMEM>>>(src1p, W1, bf1, ff1p, NR, PFF, DD);
    mma_gemm_kernel<false, false><<<gD, blk, GEMM_SMEM>>>(ff1p, W2, bf2, tmpp, NR, DD, PFF);
    // residual + LN 2 -> output
    ln_kernel<<<NR, blk>>>(src1p, tmpp, g2, b2, out);
}

// round 6
// speedup vs baseline: 2.3018x; 1.4668x over previous
#include <cuda_runtime.h>
#include <cstdint>

// Problem constants
#define BB  4
#define SS  2048
#define DD  1024
#define HH  16
#define HDD 64
#define PFF 4096
#define NR  (BB * SS)   // 8192 rows

// ---------------------------------------------------------------------------
// Scratch (static __device__ — no allocation allowed)
// ---------------------------------------------------------------------------
__device__ float g_q[BB * HH * SS * HDD];     // 32 MB, [b][h][s][d]
__device__ float g_k[BB * HH * SS * HDD];     // 32 MB
__device__ float g_v[BB * HH * SS * HDD];     // 32 MB
__device__ float g_attn[NR * DD];             // 32 MB
__device__ float g_tmp[NR * DD];              // 32 MB
__device__ float g_src1[NR * DD];             // 32 MB
__device__ float g_ff1[NR * PFF];             // 128 MB

__device__ __forceinline__ uint32_t f2tf32(float x) {
    uint32_t y;
    asm("cvt.rna.tf32.f32 %0, %1;" : "=r"(y) : "f"(x));
    return y;
}

__device__ __forceinline__ void cp16(uint32_t dst_smem, const void* src) {
    asm volatile("cp.async.cg.shared.global [%0], [%1], 16;\n" ::
                 "r"(dst_smem), "l"(src));
}

__device__ __forceinline__ void mma_tf32(float& c0, float& c1, float& c2, float& c3,
                                         uint32_t a0, uint32_t a1, uint32_t a2, uint32_t a3,
                                         uint32_t b0, uint32_t b1) {
    asm volatile(
        "mma.sync.aligned.m16n8k8.row.col.f32.tf32.tf32.f32 "
        "{%0,%1,%2,%3}, {%4,%5,%6,%7}, {%8,%9}, {%0,%1,%2,%3};\n"
        : "+f"(c0), "+f"(c1), "+f"(c2), "+f"(c3)
        : "r"(a0), "r"(a1), "r"(a2), "r"(a3), "r"(b0), "r"(b1));
}

// ---------------------------------------------------------------------------
// TF32 tensor-core GEMM (unchanged from R3 — known good at 4418us total)
// ---------------------------------------------------------------------------
#define BM 128
#define BN 128
#define BK 32
#define ASTRIDE 36
#define BSTRIDE 132
#define ASZ (BM * ASTRIDE)
#define BSZ (BK * BSTRIDE)
#define SMEM_FLOATS (2 * (ASZ + BSZ))

template <bool RELU, bool BHSD>
__global__ __launch_bounds__(256)
void mma_gemm_kernel(const float* __restrict__ A, const float* __restrict__ W,
                     const float* __restrict__ bias, float* __restrict__ C,
                     int M, int N, int K)
{
    extern __shared__ float sm[];
    float* sA[2] = { sm, sm + ASZ };
    float* sB[2] = { sm + 2 * ASZ, sm + 2 * ASZ + BSZ };

    const int tid  = threadIdx.x;
    const int lane = tid & 31;
    const int warp = tid >> 5;
    const int wm   = warp >> 2;
    const int wn   = warp & 3;
    const int bm   = blockIdx.y * BM;
    const int bn   = blockIdx.x * BN;

    const int a_row = tid >> 3;
    const int a_col = (tid & 7) * 4;
    const int b_row = tid >> 5;
    const int b_col = (tid & 31) * 4;

    const float* Ag = A + (size_t)(bm + a_row) * K + a_col;
    const float* Bg = W + (size_t)b_row * N + bn + b_col;

    uint32_t sA_dst[2], sB_dst[2];
    sA_dst[0] = (uint32_t)__cvta_generic_to_shared(sA[0] + a_row * ASTRIDE + a_col);
    sA_dst[1] = (uint32_t)__cvta_generic_to_shared(sA[1] + a_row * ASTRIDE + a_col);
    sB_dst[0] = (uint32_t)__cvta_generic_to_shared(sB[0] + b_row * BSTRIDE + b_col);
    sB_dst[1] = (uint32_t)__cvta_generic_to_shared(sB[1] + b_row * BSTRIDE + b_col);

    const int nk = K / BK;

    {
#pragma unroll
        for (int p = 0; p < 4; p++)
            cp16(sA_dst[0] + p * 32 * ASTRIDE * 4, Ag + (size_t)p * 32 * K);
#pragma unroll
        for (int p = 0; p < 4; p++)
            cp16(sB_dst[0] + p * 8 * BSTRIDE * 4, Bg + (size_t)p * 8 * N);
        asm volatile("cp.async.commit_group;\n" ::);
    }

    float acc[4][4][4];
#pragma unroll
    for (int i = 0; i < 4; i++)
#pragma unroll
        for (int j = 0; j < 4; j++)
#pragma unroll
            for (int r = 0; r < 4; r++) acc[i][j][r] = 0.0f;

    const int lr = lane >> 2;
    const int lc = lane & 3;

    int buf = 0;
    for (int t = 0; t < nk; ++t) {
        asm volatile("cp.async.wait_group 0;\n" ::);
        __syncthreads();

        if (t + 1 < nk) {
            const float* Agn = Ag + (size_t)(t + 1) * BK;
            const float* Bgn = Bg + (size_t)(t + 1) * BK * N;
            const int nb = buf ^ 1;
#pragma unroll
            for (int p = 0; p < 4; p++)
                cp16(sA_dst[nb] + p * 32 * ASTRIDE * 4, Agn + (size_t)p * 32 * K);
#pragma unroll
            for (int p = 0; p < 4; p++)
                cp16(sB_dst[nb] + p * 8 * BSTRIDE * 4, Bgn + (size_t)p * 8 * N);
            asm volatile("cp.async.commit_group;\n" ::);
        }

        const float* __restrict__ sAb = sA[buf];
        const float* __restrict__ sBb = sB[buf];

#pragma unroll
        for (int kk = 0; kk < 4; ++kk) {
            const int k0 = kk * 8 + lc;
            uint32_t af[4][4];
#pragma unroll
            for (int mt = 0; mt < 4; mt++) {
                const int r0 = wm * 64 + mt * 16 + lr;
                af[mt][0] = f2tf32(sAb[r0 * ASTRIDE + k0]);
                af[mt][1] = f2tf32(sAb[(r0 + 8) * ASTRIDE + k0]);
                af[mt][2] = f2tf32(sAb[r0 * ASTRIDE + k0 + 4]);
                af[mt][3] = f2tf32(sAb[(r0 + 8) * ASTRIDE + k0 + 4]);
            }
            uint32_t bf[4][2];
#pragma unroll
            for (int nt = 0; nt < 4; nt++) {
                const int c0 = wn * 32 + nt * 8 + lr;
                bf[nt][0] = f2tf32(sBb[(kk * 8 + lc) * BSTRIDE + c0]);
                bf[nt][1] = f2tf32(sBb[(kk * 8 + 4 + lc) * BSTRIDE + c0]);
            }
#pragma unroll
            for (int mt = 0; mt < 4; mt++)
#pragma unroll
                for (int nt = 0; nt < 4; nt++)
                    mma_tf32(acc[mt][nt][0], acc[mt][nt][1],
                             acc[mt][nt][2], acc[mt][nt][3],
                             af[mt][0], af[mt][1], af[mt][2], af[mt][3],
                             bf[nt][0], bf[nt][1]);
        }
        buf ^= 1;
    }

#pragma unroll
    for (int mt = 0; mt < 4; mt++) {
#pragma unroll
        for (int nt = 0; nt < 4; nt++) {
            const int col = bn + wn * 32 + nt * 8 + lc * 2;
            const float bv0 = bias[col];
            const float bv1 = bias[col + 1];
#pragma unroll
            for (int half = 0; half < 2; half++) {
                const int row = bm + wm * 64 + mt * 16 + lr + half * 8;
                float v0 = acc[mt][nt][half * 2 + 0] + bv0;
                float v1 = acc[mt][nt][half * 2 + 1] + bv1;
                if (RELU) { v0 = fmaxf(v0, 0.0f); v1 = fmaxf(v1, 0.0f); }
                float* dst;
                if (BHSD) {
                    const int b_ = row >> 11;
                    const int s_ = row & 2047;
                    const int h_ = col >> 6;
                    const int d_ = col & 63;
                    dst = C + ((size_t)(b_ * HH + h_) * SS + s_) * HDD + d_;
                } else {
                    dst = C + (size_t)row * N + col;
                }
                *(float2*)dst = make_float2(v0, v1);
            }
        }
    }
}

// ---------------------------------------------------------------------------
// Flash attention with TF32 mma.
// 128 threads = 4 warps; each warp owns 16 query rows of a 64-query tile.
// Q held in registers as A-fragments (loaded once). K/V converted to tf32 at
// smem store. P staged per-warp in smem (tf32) to re-fragment for PV.
// ---------------------------------------------------------------------------
#define KS_STRIDE 68   // bank = 4*lr + lc + const  -> conflict-free
#define VS_STRIDE 72   // bank = 8*lc + lr + const  -> conflict-free
#define PS_STRIDE 68
#define FLASH_SMEM_BYTES ((64 * KS_STRIDE + 64 * VS_STRIDE + 64 * PS_STRIDE) * 4)

__global__ __launch_bounds__(128)
void flash_mma_kernel(const float* __restrict__ Q, const float* __restrict__ Kg,
                      const float* __restrict__ Vg, float* __restrict__ Og)
{
    extern __shared__ float sm[];
    float* Ks = sm;                               // [64][KS_STRIDE] tf32 bits
    float* Vs = Ks + 64 * KS_STRIDE;              // [64][VS_STRIDE] tf32 bits
    float* Ps = Vs + 64 * VS_STRIDE;              // 4 x [16][PS_STRIDE] tf32 bits

    const int tid  = threadIdx.x;
    const int warp = tid >> 5;
    const int lane = tid & 31;
    const int lr   = lane >> 2;   // 0..7
    const int lc   = lane & 3;    // 0..3
    const int bh   = blockIdx.y;
    const int q0   = blockIdx.x * 64;

    const float* qb = Q  + (size_t)bh * SS * HDD;
    const float* kb = Kg + (size_t)bh * SS * HDD;
    const float* vb = Vg + (size_t)bh * SS * HDD;

    // Q A-fragments, pre-scaled by 1/sqrt(64), kept in registers for all tiles
    uint32_t aq[8][4];
    {
        const int r0 = q0 + warp * 16 + lr;
#pragma unroll
        for (int kk = 0; kk < 8; kk++) {
            const int c = kk * 8 + lc;
            aq[kk][0] = f2tf32(qb[(size_t)r0 * HDD + c] * 0.125f);
            aq[kk][1] = f2tf32(qb[(size_t)(r0 + 8) * HDD + c] * 0.125f);
            aq[kk][2] = f2tf32(qb[(size_t)r0 * HDD + c + 4] * 0.125f);
            aq[kk][3] = f2tf32(qb[(size_t)(r0 + 8) * HDD + c + 4] * 0.125f);
        }
    }

    float o[8][4];
#pragma unroll
    for (int n = 0; n < 8; n++)
#pragma unroll
        for (int r = 0; r < 4; r++) o[n][r] = 0.0f;
    float m0 = -3.0e38f, m1 = -3.0e38f, l0 = 0.0f, l1 = 0.0f;

    float* Pw = Ps + warp * 16 * PS_STRIDE;

    for (int kt = 0; kt < SS / 64; ++kt) {
        __syncthreads();   // prior-iter readers of Ks/Vs done
        // load + convert K,V tile (64x64 fp32 -> tf32 bits in smem)
        const float4* kp = (const float4*)(kb + (size_t)kt * 64 * HDD);
        const float4* vp = (const float4*)(vb + (size_t)kt * 64 * HDD);
#pragma unroll
        for (int p = 0; p < 8; p++) {
            const int idx = tid + p * 128;      // float4 index, 0..1023
            const int row = idx >> 4;
            const int c4  = (idx & 15) << 2;
            float4 kv = kp[idx];
            uint4 kq;
            kq.x = f2tf32(kv.x); kq.y = f2tf32(kv.y);
            kq.z = f2tf32(kv.z); kq.w = f2tf32(kv.w);
            *(uint4*)(Ks + row * KS_STRIDE + c4) = kq;
            float4 vv = vp[idx];
            uint4 vq;
            vq.x = f2tf32(vv.x); vq.y = f2tf32(vv.y);
            vq.z = f2tf32(vv.z); vq.w = f2tf32(vv.w);
            *(uint4*)(Vs + row * VS_STRIDE + c4) = vq;
        }
        __syncthreads();

        // S = Q @ K^T  (16x64 per warp)
        float s[8][4];
#pragma unroll
        for (int n = 0; n < 8; n++)
#pragma unroll
            for (int r = 0; r < 4; r++) s[n][r] = 0.0f;

        const uint32_t* Ku = (const uint32_t*)Ks;
#pragma unroll
        for (int kk = 0; kk < 8; kk++) {
            const int kc = kk * 8 + lc;
#pragma unroll
            for (int n = 0; n < 8; n++) {
                const uint32_t b0 = Ku[(n * 8 + lr) * KS_STRIDE + kc];
                const uint32_t b1 = Ku[(n * 8 + lr) * KS_STRIDE + kc + 4];
                mma_tf32(s[n][0], s[n][1], s[n][2], s[n][3],
                         aq[kk][0], aq[kk][1], aq[kk][2], aq[kk][3], b0, b1);
            }
        }

        // online softmax, two rows per thread (lr and lr+8)
        float mx0 = -3.0e38f, mx1 = -3.0e38f;
#pragma unroll
        for (int n = 0; n < 8; n++) {
            mx0 = fmaxf(mx0, fmaxf(s[n][0], s[n][1]));
            mx1 = fmaxf(mx1, fmaxf(s[n][2], s[n][3]));
        }
        mx0 = fmaxf(mx0, __shfl_xor_sync(0xffffffffu, mx0, 1));
        mx0 = fmaxf(mx0, __shfl_xor_sync(0xffffffffu, mx0, 2));
        mx1 = fmaxf(mx1, __shfl_xor_sync(0xffffffffu, mx1, 1));
        mx1 = fmaxf(mx1, __shfl_xor_sync(0xffffffffu, mx1, 2));

        const float mn0 = fmaxf(m0, mx0);
        const float mn1 = fmaxf(m1, mx1);
        const float al0 = __expf(m0 - mn0);
        const float al1 = __expf(m1 - mn1);
        m0 = mn0; m1 = mn1;

        float rs0 = 0.0f, rs1 = 0.0f;
#pragma unroll
        for (int n = 0; n < 8; n++) {
            s[n][0] = __expf(s[n][0] - mn0);
            s[n][1] = __expf(s[n][1] - mn0);
            s[n][2] = __expf(s[n][2] - mn1);
            s[n][3] = __expf(s[n][3] - mn1);
            rs0 += s[n][0] + s[n][1];
            rs1 += s[n][2] + s[n][3];
        }
        rs0 += __shfl_xor_sync(0xffffffffu, rs0, 1);
        rs0 += __shfl_xor_sync(0xffffffffu, rs0, 2);
        rs1 += __shfl_xor_sync(0xffffffffu, rs1, 1);
        rs1 += __shfl_xor_sync(0xffffffffu, rs1, 2);
        l0 = l0 * al0 + rs0;
        l1 = l1 * al1 + rs1;

#pragma unroll
        for (int n = 0; n < 8; n++) {
            o[n][0] *= al0; o[n][1] *= al0;
            o[n][2] *= al1; o[n][3] *= al1;
        }

        // stage P (tf32 bits) for A-fragment reads
#pragma unroll
        for (int n = 0; n < 8; n++) {
            uint2 p01; p01.x = f2tf32(s[n][0]); p01.y = f2tf32(s[n][1]);
            *(uint2*)(Pw + lr * PS_STRIDE + n * 8 + 2 * lc) = p01;
            uint2 p23; p23.x = f2tf32(s[n][2]); p23.y = f2tf32(s[n][3]);
            *(uint2*)(Pw + (lr + 8) * PS_STRIDE + n * 8 + 2 * lc) = p23;
        }
        __syncwarp();

        // O += P @ V
        const uint32_t* Pu = (const uint32_t*)Pw;
        const uint32_t* Vu = (const uint32_t*)Vs;
#pragma unroll
        for (int kk = 0; kk < 8; kk++) {
            const int kc = kk * 8 + lc;
            const uint32_t a0 = Pu[lr * PS_STRIDE + kc];
            const uint32_t a1 = Pu[(lr + 8) * PS_STRIDE + kc];
            const uint32_t a2 = Pu[lr * PS_STRIDE + kc + 4];
            const uint32_t a3 = Pu[(lr + 8) * PS_STRIDE + kc + 4];
#pragma unroll
            for (int n = 0; n < 8; n++) {
                const uint32_t b0 = Vu[kc * VS_STRIDE + n * 8 + lr];
                const uint32_t b1 = Vu[(kc + 4) * VS_STRIDE + n * 8 + lr];
                mma_tf32(o[n][0], o[n][1], o[n][2], o[n][3],
                         a0, a1, a2, a3, b0, b1);
            }
        }
        __syncwarp();   // P reads done before next-iter overwrite
    }

    // epilogue: normalize and write [B,S,D] rows
    const float inv0 = 1.0f / l0;
    const float inv1 = 1.0f / l1;
    const int b_ = bh >> 4;
    const int h_ = bh & 15;
    const size_t row0 = (size_t)b_ * SS + q0 + warp * 16 + lr;
    float* d0 = Og + row0 * DD + h_ * HDD;
    float* d1 = Og + (row0 + 8) * DD + h_ * HDD;
#pragma unroll
    for (int n = 0; n < 8; n++) {
        *(float2*)(d0 + n * 8 + 2 * lc) = make_float2(o[n][0] * inv0, o[n][1] * inv0);
        *(float2*)(d1 + n * 8 + 2 * lc) = make_float2(o[n][2] * inv1, o[n][3] * inv1);
    }
}

// ---------------------------------------------------------------------------
// Fused residual + LayerNorm
// ---------------------------------------------------------------------------
__global__ __launch_bounds__(256)
void ln_kernel(const float* __restrict__ x1, const float* __restrict__ x2,
               const float* __restrict__ gamma, const float* __restrict__ beta,
               float* __restrict__ out)
{
    const int row = blockIdx.x;
    const int tid = threadIdx.x;
    const float4 a = ((const float4*)(x1 + (size_t)row * DD))[tid];
    const float4 b = ((const float4*)(x2 + (size_t)row * DD))[tid];
    float4 x = make_float4(a.x + b.x, a.y + b.y, a.z + b.z, a.w + b.w);

    float s = x.x + x.y + x.z + x.w;
    float q = x.x * x.x + x.y * x.y + x.z * x.z + x.w * x.w;

    __shared__ float shs[8], shq[8];
    const int lane = tid & 31, wid = tid >> 5;
#pragma unroll
    for (int o = 16; o; o >>= 1) {
        s += __shfl_xor_sync(0xffffffffu, s, o);
        q += __shfl_xor_sync(0xffffffffu, q, o);
    }
    if (lane == 0) { shs[wid] = s; shq[wid] = q; }
    __syncthreads();
    if (tid == 0) {
        float ts = 0.0f, tq = 0.0f;
#pragma unroll
        for (int i = 0; i < 8; i++) { ts += shs[i]; tq += shq[i]; }
        shs[0] = ts; shq[0] = tq;
    }
    __syncthreads();
    const float mean = shs[0] * (1.0f / DD);
    const float var  = shq[0] * (1.0f / DD) - mean * mean;
    const float rstd = rsqrtf(var + 1e-5f);

    const float4 g  = ((const float4*)gamma)[tid];
    const float4 be = ((const float4*)beta)[tid];
    float4 o;
    o.x = (x.x - mean) * rstd * g.x + be.x;
    o.y = (x.y - mean) * rstd * g.y + be.y;
    o.z = (x.z - mean) * rstd * g.z + be.z;
    o.w = (x.w - mean) * rstd * g.w + be.w;
    ((float4*)(out + (size_t)row * DD))[tid] = o;
}

// ---------------------------------------------------------------------------
// Launch
// ---------------------------------------------------------------------------
extern "C" void kernel_launch(void* const* d_in, const int* in_sizes, int n_in,
                              void* d_out, int out_size)
{
    const float* src = (const float*)d_in[0];
    const float* Wq  = (const float*)d_in[1];
    const float* bq  = (const float*)d_in[2];
    const float* Wk  = (const float*)d_in[3];
    const float* bk  = (const float*)d_in[4];
    const float* Wv  = (const float*)d_in[5];
    const float* bv  = (const float*)d_in[6];
    const float* Wo  = (const float*)d_in[7];
    const float* bo  = (const float*)d_in[8];
    const float* g1  = (const float*)d_in[9];
    const float* b1  = (const float*)d_in[10];
    const float* W1  = (const float*)d_in[11];
    const float* bf1 = (const float*)d_in[12];
    const float* W2  = (const float*)d_in[13];
    const float* bf2 = (const float*)d_in[14];
    const float* g2  = (const float*)d_in[15];
    const float* b2  = (const float*)d_in[16];
    float* out = (float*)d_out;

    float *qp, *kp, *vp, *attnp, *tmpp, *src1p, *ff1p;
    cudaGetSymbolAddress((void**)&qp,    g_q);
    cudaGetSymbolAddress((void**)&kp,    g_k);
    cudaGetSymbolAddress((void**)&vp,    g_v);
    cudaGetSymbolAddress((void**)&attnp, g_attn);
    cudaGetSymbolAddress((void**)&tmpp,  g_tmp);
    cudaGetSymbolAddress((void**)&src1p, g_src1);
    cudaGetSymbolAddress((void**)&ff1p,  g_ff1);

    const int GEMM_SMEM = SMEM_FLOATS * 4;   // 70656 B

    cudaFuncSetAttribute(mma_gemm_kernel<false, true>,
                         cudaFuncAttributeMaxDynamicSharedMemorySize, GEMM_SMEM);
    cudaFuncSetAttribute(mma_gemm_kernel<false, false>,
                         cudaFuncAttributeMaxDynamicSharedMemorySize, GEMM_SMEM);
    cudaFuncSetAttribute(mma_gemm_kernel<true, false>,
                         cudaFuncAttributeMaxDynamicSharedMemorySize, GEMM_SMEM);
    cudaFuncSetAttribute(flash_mma_kernel,
                         cudaFuncAttributeMaxDynamicSharedMemorySize, FLASH_SMEM_BYTES);

    dim3 blk(256);
    dim3 gD(DD / BN, NR / BM);     // (8, 64)
    dim3 gPF(PFF / BN, NR / BM);   // (32, 64)
    dim3 gF(SS / 64, BB * HH);     // (32, 64)

    // QKV projections -> [B,H,S,HD]
    mma_gemm_kernel<false, true><<<gD, blk, GEMM_SMEM>>>(src, Wq, bq, qp, NR, DD, DD);
    mma_gemm_kernel<false, true><<<gD, blk, GEMM_SMEM>>>(src, Wk, bk, kp, NR, DD, DD);
    mma_gemm_kernel<false, true><<<gD, blk, GEMM_SMEM>>>(src, Wv, bv, vp, NR, DD, DD);
    // attention (tensor-core flash)
    flash_mma_kernel<<<gF, dim3(128), FLASH_SMEM_BYTES>>>(qp, kp, vp, attnp);
    // O projection
    mma_gemm_kernel<false, false><<<gD, blk, GEMM_SMEM>>>(attnp, Wo, bo, tmpp, NR, DD, DD);
    // residual + LN 1
    ln_kernel<<<NR, blk>>>(src, tmpp, g1, b1, src1p);
    // FFN
    mma_gemm_kernel<true, false><<<gPF, blk, GEMM_SMEM>>>(src1p, W1, bf1, ff1p, NR, PFF, DD);
    mma_gemm_kernel<false, false><<<gD, blk, GEMM_SMEM>>>(ff1p, W2, bf2, tmpp, NR, DD, PFF);
    // residual + LN 2 -> output
    ln_kernel<<<NR, blk>>>(src1p, tmpp, g2, b2, out);
}

// round 7
// speedup vs baseline: 2.5484x; 1.1071x over previous
#include <cuda_runtime.h>
#include <cstdint>

// Problem constants
#define BB  4
#define SS  2048
#define DD  1024
#define HH  16
#define HDD 64
#define PFF 4096
#define NR  (BB * SS)   // 8192 rows

// ---------------------------------------------------------------------------
// Scratch (static __device__ — no allocation allowed)
// All "tf32" buffers hold fp32 bit patterns pre-rounded with cvt.rna.tf32.
// ---------------------------------------------------------------------------
__device__ float g_q[BB * HH * SS * HDD];     // tf32 bits, [b][h][s][d]
__device__ float g_k[BB * HH * SS * HDD];     // tf32 bits
__device__ float g_v[BB * HH * SS * HDD];     // tf32 bits
__device__ float g_attn[NR * DD];             // tf32 bits
__device__ float g_tmp[NR * DD];              // fp32
__device__ float g_src1[NR * DD];             // fp32
__device__ float g_src1_t[NR * DD];           // tf32 bits
__device__ float g_src_t[NR * DD];            // tf32 bits
__device__ float g_ff1[NR * PFF];             // tf32 bits (ReLU applied)
__device__ float g_wt[12 * 1024 * 1024];      // tf32 bits: Wq|Wk|Wv|Wo|W1|W2

#define WT_WQ 0
#define WT_WK (1024 * 1024)
#define WT_WV (2 * 1024 * 1024)
#define WT_WO (3 * 1024 * 1024)
#define WT_W1 (4 * 1024 * 1024)
#define WT_W2 (8 * 1024 * 1024)

__device__ __forceinline__ uint32_t f2tf32(float x) {
    uint32_t y;
    asm("cvt.rna.tf32.f32 %0, %1;" : "=r"(y) : "f"(x));
    return y;
}

__device__ __forceinline__ void cp16(uint32_t dst_smem, const void* src) {
    asm volatile("cp.async.cg.shared.global [%0], [%1], 16;\n" ::
                 "r"(dst_smem), "l"(src));
}

__device__ __forceinline__ void mma_tf32(float& c0, float& c1, float& c2, float& c3,
                                         uint32_t a0, uint32_t a1, uint32_t a2, uint32_t a3,
                                         uint32_t b0, uint32_t b1) {
    asm volatile(
        "mma.sync.aligned.m16n8k8.row.col.f32.tf32.tf32.f32 "
        "{%0,%1,%2,%3}, {%4,%5,%6,%7}, {%8,%9}, {%0,%1,%2,%3};\n"
        : "+f"(c0), "+f"(c1), "+f"(c2), "+f"(c3)
        : "r"(a0), "r"(a1), "r"(a2), "r"(a3), "r"(b0), "r"(b1));
}

// ---------------------------------------------------------------------------
// Elementwise fp32 -> tf32-bits conversion (vectorized)
// ---------------------------------------------------------------------------
__global__ __launch_bounds__(256)
void cvt_tf32_kernel(const float4* __restrict__ in, uint4* __restrict__ out, int n4)
{
    const int i = blockIdx.x * blockDim.x + threadIdx.x;
    if (i < n4) {
        float4 v = in[i];
        uint4 o;
        o.x = f2tf32(v.x); o.y = f2tf32(v.y);
        o.z = f2tf32(v.z); o.w = f2tf32(v.w);
        out[i] = o;
    }
}

// ---------------------------------------------------------------------------
// TF32 tensor-core GEMM. A and W are PRE-ROUNDED tf32 bits — inner loop has
// no cvt, only LDS + MMA. CVT_OUT=1 writes tf32 bits (for GEMM/flash consumers),
// else fp32.
// ---------------------------------------------------------------------------
#define BM 128
#define BN 128
#define BK 32
#define ASTRIDE 36
#define BSTRIDE 132
#define ASZ (BM * ASTRIDE)
#define BSZ (BK * BSTRIDE)
#define SMEM_FLOATS (2 * (ASZ + BSZ))

template <bool RELU, bool BHSD, bool CVT_OUT>
__global__ __launch_bounds__(256)
void mma_gemm_kernel(const float* __restrict__ A, const float* __restrict__ W,
                     const float* __restrict__ bias, float* __restrict__ C,
                     int M, int N, int K)
{
    extern __shared__ float sm[];
    float* sA[2] = { sm, sm + ASZ };
    float* sB[2] = { sm + 2 * ASZ, sm + 2 * ASZ + BSZ };

    const int tid  = threadIdx.x;
    const int lane = tid & 31;
    const int warp = tid >> 5;
    const int wm   = warp >> 2;
    const int wn   = warp & 3;
    const int bm   = blockIdx.y * BM;
    const int bn   = blockIdx.x * BN;

    const int a_row = tid >> 3;
    const int a_col = (tid & 7) * 4;
    const int b_row = tid >> 5;
    const int b_col = (tid & 31) * 4;

    const float* Ag = A + (size_t)(bm + a_row) * K + a_col;
    const float* Bg = W + (size_t)b_row * N + bn + b_col;

    uint32_t sA_dst[2], sB_dst[2];
    sA_dst[0] = (uint32_t)__cvta_generic_to_shared(sA[0] + a_row * ASTRIDE + a_col);
    sA_dst[1] = (uint32_t)__cvta_generic_to_shared(sA[1] + a_row * ASTRIDE + a_col);
    sB_dst[0] = (uint32_t)__cvta_generic_to_shared(sB[0] + b_row * BSTRIDE + b_col);
    sB_dst[1] = (uint32_t)__cvta_generic_to_shared(sB[1] + b_row * BSTRIDE + b_col);

    const int nk = K / BK;

    {
#pragma unroll
        for (int p = 0; p < 4; p++)
            cp16(sA_dst[0] + p * 32 * ASTRIDE * 4, Ag + (size_t)p * 32 * K);
#pragma unroll
        for (int p = 0; p < 4; p++)
            cp16(sB_dst[0] + p * 8 * BSTRIDE * 4, Bg + (size_t)p * 8 * N);
        asm volatile("cp.async.commit_group;\n" ::);
    }

    float acc[4][4][4];
#pragma unroll
    for (int i = 0; i < 4; i++)
#pragma unroll
        for (int j = 0; j < 4; j++)
#pragma unroll
            for (int r = 0; r < 4; r++) acc[i][j][r] = 0.0f;

    const int lr = lane >> 2;
    const int lc = lane & 3;

    int buf = 0;
    for (int t = 0; t < nk; ++t) {
        asm volatile("cp.async.wait_group 0;\n" ::);
        __syncthreads();

        if (t + 1 < nk) {
            const float* Agn = Ag + (size_t)(t + 1) * BK;
            const float* Bgn = Bg + (size_t)(t + 1) * BK * N;
            const int nb = buf ^ 1;
#pragma unroll
            for (int p = 0; p < 4; p++)
                cp16(sA_dst[nb] + p * 32 * ASTRIDE * 4, Agn + (size_t)p * 32 * K);
#pragma unroll
            for (int p = 0; p < 4; p++)
                cp16(sB_dst[nb] + p * 8 * BSTRIDE * 4, Bgn + (size_t)p * 8 * N);
            asm volatile("cp.async.commit_group;\n" ::);
        }

        const uint32_t* __restrict__ Au = (const uint32_t*)sA[buf];
        const uint32_t* __restrict__ Bu = (const uint32_t*)sB[buf];

#pragma unroll
        for (int kk = 0; kk < 4; ++kk) {
            const int k0 = kk * 8 + lc;
            uint32_t af[4][4];
#pragma unroll
            for (int mt = 0; mt < 4; mt++) {
                const int r0 = wm * 64 + mt * 16 + lr;
                af[mt][0] = Au[r0 * ASTRIDE + k0];
                af[mt][1] = Au[(r0 + 8) * ASTRIDE + k0];
                af[mt][2] = Au[r0 * ASTRIDE + k0 + 4];
                af[mt][3] = Au[(r0 + 8) * ASTRIDE + k0 + 4];
            }
            uint32_t bf[4][2];
#pragma unroll
            for (int nt = 0; nt < 4; nt++) {
                const int c0 = wn * 32 + nt * 8 + lr;
                bf[nt][0] = Bu[(kk * 8 + lc) * BSTRIDE + c0];
                bf[nt][1] = Bu[(kk * 8 + 4 + lc) * BSTRIDE + c0];
            }
#pragma unroll
            for (int mt = 0; mt < 4; mt++)
#pragma unroll
                for (int nt = 0; nt < 4; nt++)
                    mma_tf32(acc[mt][nt][0], acc[mt][nt][1],
                             acc[mt][nt][2], acc[mt][nt][3],
                             af[mt][0], af[mt][1], af[mt][2], af[mt][3],
                             bf[nt][0], bf[nt][1]);
        }
        buf ^= 1;
    }

#pragma unroll
    for (int mt = 0; mt < 4; mt++) {
#pragma unroll
        for (int nt = 0; nt < 4; nt++) {
            const int col = bn + wn * 32 + nt * 8 + lc * 2;
            const float bv0 = bias[col];
            const float bv1 = bias[col + 1];
#pragma unroll
            for (int half = 0; half < 2; half++) {
                const int row = bm + wm * 64 + mt * 16 + lr + half * 8;
                float v0 = acc[mt][nt][half * 2 + 0] + bv0;
                float v1 = acc[mt][nt][half * 2 + 1] + bv1;
                if (RELU) { v0 = fmaxf(v0, 0.0f); v1 = fmaxf(v1, 0.0f); }
                if (CVT_OUT) {
                    v0 = __uint_as_float(f2tf32(v0));
                    v1 = __uint_as_float(f2tf32(v1));
                }
                float* dst;
                if (BHSD) {
                    const int b_ = row >> 11;
                    const int s_ = row & 2047;
                    const int h_ = col >> 6;
                    const int d_ = col & 63;
                    dst = C + ((size_t)(b_ * HH + h_) * SS + s_) * HDD + d_;
                } else {
                    dst = C + (size_t)row * N + col;
                }
                *(float2*)dst = make_float2(v0, v1);
            }
        }
    }
}

// ---------------------------------------------------------------------------
// Flash attention, TF32 mma. Q/K/V arrive as PRE-ROUNDED tf32 bits, so the
// K/V smem fill and Q fragment build are pure copies (no cvt). Output is
// written as tf32 bits for the O-projection GEMM.
// ---------------------------------------------------------------------------
#define KS_STRIDE 68
#define VS_STRIDE 72
#define PS_STRIDE 68
#define FLASH_SMEM_BYTES ((64 * KS_STRIDE + 64 * VS_STRIDE + 64 * PS_STRIDE) * 4)

__global__ __launch_bounds__(128)
void flash_mma_kernel(const float* __restrict__ Q, const float* __restrict__ Kg,
                      const float* __restrict__ Vg, float* __restrict__ Og)
{
    extern __shared__ float sm[];
    float* Ks = sm;                               // [64][KS_STRIDE]
    float* Vs = Ks + 64 * KS_STRIDE;              // [64][VS_STRIDE]
    float* Ps = Vs + 64 * VS_STRIDE;              // 4 x [16][PS_STRIDE]

    const int tid  = threadIdx.x;
    const int warp = tid >> 5;
    const int lane = tid & 31;
    const int lr   = lane >> 2;
    const int lc   = lane & 3;
    const int bh   = blockIdx.y;
    const int q0   = blockIdx.x * 64;

    const float* qb = Q  + (size_t)bh * SS * HDD;
    const float* kb = Kg + (size_t)bh * SS * HDD;
    const float* vb = Vg + (size_t)bh * SS * HDD;

    // Q fragments: values already tf32-rounded; *0.125f (2^-3) is exact and
    // commutes with tf32 rounding, so no cvt needed.
    uint32_t aq[8][4];
    {
        const int r0 = q0 + warp * 16 + lr;
#pragma unroll
        for (int kk = 0; kk < 8; kk++) {
            const int c = kk * 8 + lc;
            aq[kk][0] = __float_as_uint(qb[(size_t)r0 * HDD + c] * 0.125f);
            aq[kk][1] = __float_as_uint(qb[(size_t)(r0 + 8) * HDD + c] * 0.125f);
            aq[kk][2] = __float_as_uint(qb[(size_t)r0 * HDD + c + 4] * 0.125f);
            aq[kk][3] = __float_as_uint(qb[(size_t)(r0 + 8) * HDD + c + 4] * 0.125f);
        }
    }

    float o[8][4];
#pragma unroll
    for (int n = 0; n < 8; n++)
#pragma unroll
        for (int r = 0; r < 4; r++) o[n][r] = 0.0f;
    float m0 = -3.0e38f, m1 = -3.0e38f, l0 = 0.0f, l1 = 0.0f;

    float* Pw = Ps + warp * 16 * PS_STRIDE;

    for (int kt = 0; kt < SS / 64; ++kt) {
        __syncthreads();
        const float4* kp = (const float4*)(kb + (size_t)kt * 64 * HDD);
        const float4* vp = (const float4*)(vb + (size_t)kt * 64 * HDD);
#pragma unroll
        for (int p = 0; p < 8; p++) {
            const int idx = tid + p * 128;
            const int row = idx >> 4;
            const int c4  = (idx & 15) << 2;
            *(float4*)(Ks + row * KS_STRIDE + c4) = kp[idx];
            *(float4*)(Vs + row * VS_STRIDE + c4) = vp[idx];
        }
        __syncthreads();

        // S = Q @ K^T
        float s[8][4];
#pragma unroll
        for (int n = 0; n < 8; n++)
#pragma unroll
            for (int r = 0; r < 4; r++) s[n][r] = 0.0f;

        const uint32_t* Ku = (const uint32_t*)Ks;
#pragma unroll
        for (int kk = 0; kk < 8; kk++) {
            const int kc = kk * 8 + lc;
#pragma unroll
            for (int n = 0; n < 8; n++) {
                const uint32_t b0 = Ku[(n * 8 + lr) * KS_STRIDE + kc];
                const uint32_t b1 = Ku[(n * 8 + lr) * KS_STRIDE + kc + 4];
                mma_tf32(s[n][0], s[n][1], s[n][2], s[n][3],
                         aq[kk][0], aq[kk][1], aq[kk][2], aq[kk][3], b0, b1);
            }
        }

        // online softmax
        float mx0 = -3.0e38f, mx1 = -3.0e38f;
#pragma unroll
        for (int n = 0; n < 8; n++) {
            mx0 = fmaxf(mx0, fmaxf(s[n][0], s[n][1]));
            mx1 = fmaxf(mx1, fmaxf(s[n][2], s[n][3]));
        }
        mx0 = fmaxf(mx0, __shfl_xor_sync(0xffffffffu, mx0, 1));
        mx0 = fmaxf(mx0, __shfl_xor_sync(0xffffffffu, mx0, 2));
        mx1 = fmaxf(mx1, __shfl_xor_sync(0xffffffffu, mx1, 1));
        mx1 = fmaxf(mx1, __shfl_xor_sync(0xffffffffu, mx1, 2));

        const float mn0 = fmaxf(m0, mx0);
        const float mn1 = fmaxf(m1, mx1);
        const float al0 = __expf(m0 - mn0);
        const float al1 = __expf(m1 - mn1);
        m0 = mn0; m1 = mn1;

        float rs0 = 0.0f, rs1 = 0.0f;
#pragma unroll
        for (int n = 0; n < 8; n++) {
            s[n][0] = __expf(s[n][0] - mn0);
            s[n][1] = __expf(s[n][1] - mn0);
            s[n][2] = __expf(s[n][2] - mn1);
            s[n][3] = __expf(s[n][3] - mn1);
            rs0 += s[n][0] + s[n][1];
            rs1 += s[n][2] + s[n][3];
        }
        rs0 += __shfl_xor_sync(0xffffffffu, rs0, 1);
        rs0 += __shfl_xor_sync(0xffffffffu, rs0, 2);
        rs1 += __shfl_xor_sync(0xffffffffu, rs1, 1);
        rs1 += __shfl_xor_sync(0xffffffffu, rs1, 2);
        l0 = l0 * al0 + rs0;
        l1 = l1 * al1 + rs1;

#pragma unroll
        for (int n = 0; n < 8; n++) {
            o[n][0] *= al0; o[n][1] *= al0;
            o[n][2] *= al1; o[n][3] *= al1;
        }

        // stage P (tf32 bits)
#pragma unroll
        for (int n = 0; n < 8; n++) {
            uint2 p01; p01.x = f2tf32(s[n][0]); p01.y = f2tf32(s[n][1]);
            *(uint2*)(Pw + lr * PS_STRIDE + n * 8 + 2 * lc) = p01;
            uint2 p23; p23.x = f2tf32(s[n][2]); p23.y = f2tf32(s[n][3]);
            *(uint2*)(Pw + (lr + 8) * PS_STRIDE + n * 8 + 2 * lc) = p23;
        }
        __syncwarp();

        // O += P @ V
        const uint32_t* Pu = (const uint32_t*)Pw;
        const uint32_t* Vu = (const uint32_t*)Vs;
#pragma unroll
        for (int kk = 0; kk < 8; kk++) {
            const int kc = kk * 8 + lc;
            const uint32_t a0 = Pu[lr * PS_STRIDE + kc];
            const uint32_t a1 = Pu[(lr + 8) * PS_STRIDE + kc];
            const uint32_t a2 = Pu[lr * PS_STRIDE + kc + 4];
            const uint32_t a3 = Pu[(lr + 8) * PS_STRIDE + kc + 4];
#pragma unroll
            for (int n = 0; n < 8; n++) {
                const uint32_t b0 = Vu[kc * VS_STRIDE + n * 8 + lr];
                const uint32_t b1 = Vu[(kc + 4) * VS_STRIDE + n * 8 + lr];
                mma_tf32(o[n][0], o[n][1], o[n][2], o[n][3],
                         a0, a1, a2, a3, b0, b1);
            }
        }
        __syncwarp();
    }

    // epilogue: normalize, round to tf32 bits (consumer is the O-proj GEMM)
    const float inv0 = 1.0f / l0;
    const float inv1 = 1.0f / l1;
    const int b_ = bh >> 4;
    const int h_ = bh & 15;
    const size_t row0 = (size_t)b_ * SS + q0 + warp * 16 + lr;
    float* d0 = Og + row0 * DD + h_ * HDD;
    float* d1 = Og + (row0 + 8) * DD + h_ * HDD;
#pragma unroll
    for (int n = 0; n < 8; n++) {
        *(float2*)(d0 + n * 8 + 2 * lc) =
            make_float2(__uint_as_float(f2tf32(o[n][0] * inv0)),
                        __uint_as_float(f2tf32(o[n][1] * inv0)));
        *(float2*)(d1 + n * 8 + 2 * lc) =
            make_float2(__uint_as_float(f2tf32(o[n][2] * inv1)),
                        __uint_as_float(f2tf32(o[n][3] * inv1)));
    }
}

// ---------------------------------------------------------------------------
// Fused residual + LayerNorm. WRITE_T additionally writes a tf32-bits copy.
// ---------------------------------------------------------------------------
template <bool WRITE_T>
__global__ __launch_bounds__(256)
void ln_kernel(const float* __restrict__ x1, const float* __restrict__ x2,
               const float* __restrict__ gamma, const float* __restrict__ beta,
               float* __restrict__ out, float* __restrict__ out_t)
{
    const int row = blockIdx.x;
    const int tid = threadIdx.x;
    const float4 a = ((const float4*)(x1 + (size_t)row * DD))[tid];
    const float4 b = ((const float4*)(x2 + (size_t)row * DD))[tid];
    float4 x = make_float4(a.x + b.x, a.y + b.y, a.z + b.z, a.w + b.w);

    float s = x.x + x.y + x.z + x.w;
    float q = x.x * x.x + x.y * x.y + x.z * x.z + x.w * x.w;

    __shared__ float shs[8], shq[8];
    const int lane = tid & 31, wid = tid >> 5;
#pragma unroll
    for (int o = 16; o; o >>= 1) {
        s += __shfl_xor_sync(0xffffffffu, s, o);
        q += __shfl_xor_sync(0xffffffffu, q, o);
    }
    if (lane == 0) { shs[wid] = s; shq[wid] = q; }
    __syncthreads();
    if (tid == 0) {
        float ts = 0.0f, tq = 0.0f;
#pragma unroll
        for (int i = 0; i < 8; i++) { ts += shs[i]; tq += shq[i]; }
        shs[0] = ts; shq[0] = tq;
    }
    __syncthreads();
    const float mean = shs[0] * (1.0f / DD);
    const float var  = shq[0] * (1.0f / DD) - mean * mean;
    const float rstd = rsqrtf(var + 1e-5f);

    const float4 g  = ((const float4*)gamma)[tid];
    const float4 be = ((const float4*)beta)[tid];
    float4 o;
    o.x = (x.x - mean) * rstd * g.x + be.x;
    o.y = (x.y - mean) * rstd * g.y + be.y;
    o.z = (x.z - mean) * rstd * g.z + be.z;
    o.w = (x.w - mean) * rstd * g.w + be.w;
    ((float4*)(out + (size_t)row * DD))[tid] = o;
    if (WRITE_T) {
        float4 ot;
        ot.x = __uint_as_float(f2tf32(o.x));
        ot.y = __uint_as_float(f2tf32(o.y));
        ot.z = __uint_as_float(f2tf32(o.z));
        ot.w = __uint_as_float(f2tf32(o.w));
        ((float4*)(out_t + (size_t)row * DD))[tid] = ot;
    }
}

// ---------------------------------------------------------------------------
// Launch
// ---------------------------------------------------------------------------
extern "C" void kernel_launch(void* const* d_in, const int* in_sizes, int n_in,
                              void* d_out, int out_size)
{
    const float* src = (const float*)d_in[0];
    const float* Wq  = (const float*)d_in[1];
    const float* bq  = (const float*)d_in[2];
    const float* Wk  = (const float*)d_in[3];
    const float* bk  = (const float*)d_in[4];
    const float* Wv  = (const float*)d_in[5];
    const float* bv  = (const float*)d_in[6];
    const float* Wo  = (const float*)d_in[7];
    const float* bo  = (const float*)d_in[8];
    const float* g1  = (const float*)d_in[9];
    const float* b1  = (const float*)d_in[10];
    const float* W1  = (const float*)d_in[11];
    const float* bf1 = (const float*)d_in[12];
    const float* W2  = (const float*)d_in[13];
    const float* bf2 = (const float*)d_in[14];
    const float* g2  = (const float*)d_in[15];
    const float* b2  = (const float*)d_in[16];
    float* out = (float*)d_out;

    float *qp, *kp, *vp, *attnp, *tmpp, *src1p, *src1tp, *srctp, *ff1p, *wtp;
    cudaGetSymbolAddress((void**)&qp,     g_q);
    cudaGetSymbolAddress((void**)&kp,     g_k);
    cudaGetSymbolAddress((void**)&vp,     g_v);
    cudaGetSymbolAddress((void**)&attnp,  g_attn);
    cudaGetSymbolAddress((void**)&tmpp,   g_tmp);
    cudaGetSymbolAddress((void**)&src1p,  g_src1);
    cudaGetSymbolAddress((void**)&src1tp, g_src1_t);
    cudaGetSymbolAddress((void**)&srctp,  g_src_t);
    cudaGetSymbolAddress((void**)&ff1p,   g_ff1);
    cudaGetSymbolAddress((void**)&wtp,    g_wt);

    const int GEMM_SMEM = SMEM_FLOATS * 4;   // 70656 B

    cudaFuncSetAttribute(mma_gemm_kernel<false, true,  true>,
                         cudaFuncAttributeMaxDynamicSharedMemorySize, GEMM_SMEM);
    cudaFuncSetAttribute(mma_gemm_kernel<false, false, false>,
                         cudaFuncAttributeMaxDynamicSharedMemorySize, GEMM_SMEM);
    cudaFuncSetAttribute(mma_gemm_kernel<true,  false, true>,
                         cudaFuncAttributeMaxDynamicSharedMemorySize, GEMM_SMEM);
    cudaFuncSetAttribute(flash_mma_kernel,
                         cudaFuncAttributeMaxDynamicSharedMemorySize, FLASH_SMEM_BYTES);

    // Pre-round everything static to tf32 bits (src + 6 weight matrices)
    {
        const int T = 256;
        cvt_tf32_kernel<<<(NR * DD / 4 + T - 1) / T, T>>>(
            (const float4*)src, (uint4*)srctp, NR * DD / 4);
        cvt_tf32_kernel<<<(DD * DD / 4 + T - 1) / T, T>>>(
            (const float4*)Wq, (uint4*)(wtp + WT_WQ), DD * DD / 4);
        cvt_tf32_kernel<<<(DD * DD / 4 + T - 1) / T, T>>>(
            (const float4*)Wk, (uint4*)(wtp + WT_WK), DD * DD / 4);
        cvt_tf32_kernel<<<(DD * DD / 4 + T - 1) / T, T>>>(
            (const float4*)Wv, (uint4*)(wtp + WT_WV), DD * DD / 4);
        cvt_tf32_kernel<<<(DD * DD / 4 + T - 1) / T, T>>>(
            (const float4*)Wo, (uint4*)(wtp + WT_WO), DD * DD / 4);
        cvt_tf32_kernel<<<(DD * PFF / 4 + T - 1) / T, T>>>(
            (const float4*)W1, (uint4*)(wtp + WT_W1), DD * PFF / 4);
        cvt_tf32_kernel<<<(PFF * DD / 4 + T - 1) / T, T>>>(
            (const float4*)W2, (uint4*)(wtp + WT_W2), PFF * DD / 4);
    }

    dim3 blk(256);
    dim3 gD(DD / BN, NR / BM);     // (8, 64)
    dim3 gPF(PFF / BN, NR / BM);   // (32, 64)
    dim3 gF(SS / 64, BB * HH);     // (32, 64)

    // QKV projections -> [B,H,S,HD], outputs tf32 bits
    mma_gemm_kernel<false, true, true><<<gD, blk, GEMM_SMEM>>>(
        srctp, wtp + WT_WQ, bq, qp, NR, DD, DD);
    mma_gemm_kernel<false, true, true><<<gD, blk, GEMM_SMEM>>>(
        srctp, wtp + WT_WK, bk, kp, NR, DD, DD);
    mma_gemm_kernel<false, true, true><<<gD, blk, GEMM_SMEM>>>(
        srctp, wtp + WT_WV, bv, vp, NR, DD, DD);
    // attention (tensor-core flash), outputs tf32 bits
    flash_mma_kernel<<<gF, dim3(128), FLASH_SMEM_BYTES>>>(qp, kp, vp, attnp);
    // O projection, outputs fp32
    mma_gemm_kernel<false, false, false><<<gD, blk, GEMM_SMEM>>>(
        attnp, wtp + WT_WO, bo, tmpp, NR, DD, DD);
    // residual + LN 1 -> fp32 + tf32 copies
    ln_kernel<true><<<NR, blk>>>(src, tmpp, g1, b1, src1p, src1tp);
    // FFN1 (ReLU), outputs tf32 bits
    mma_gemm_kernel<true, false, true><<<gPF, blk, GEMM_SMEM>>>(
        src1tp, wtp + WT_W1, bf1, ff1p, NR, PFF, DD);
    // FFN2, outputs fp32
    mma_gemm_kernel<false, false, false><<<gD, blk, GEMM_SMEM>>>(
        ff1p, wtp + WT_W2, bf2, tmpp, NR, DD, PFF);
    // residual + LN 2 -> output
    ln_kernel<false><<<NR, blk>>>(src1p, tmpp, g2, b2, out, nullptr);
}

// round 8
// speedup vs baseline: 3.5338x; 1.3866x over previous
#include <cuda_runtime.h>
#include <cstdint>

// Problem constants
#define BB  4
#define SS  2048
#define DD  1024
#define HH  16
#define HDD 64
#define PFF 4096
#define NR  (BB * SS)   // 8192 rows

// ---------------------------------------------------------------------------
// Scratch (static __device__ — no allocation allowed)
// All "tf32" buffers hold fp32 bit patterns pre-rounded with cvt.rna.tf32.
// ---------------------------------------------------------------------------
__device__ float g_q[BB * HH * SS * HDD];     // tf32 bits, [b][h][s][d]
__device__ float g_k[BB * HH * SS * HDD];     // tf32 bits
__device__ float g_v[BB * HH * SS * HDD];     // tf32 bits
__device__ float g_attn[NR * DD];             // tf32 bits
__device__ float g_tmp[NR * DD];              // fp32
__device__ float g_src1[NR * DD];             // fp32
__device__ float g_src1_t[NR * DD];           // tf32 bits
__device__ float g_src_t[NR * DD];            // tf32 bits
__device__ float g_ff1[NR * PFF];             // tf32 bits (ReLU applied)
__device__ float g_wt[12 * 1024 * 1024];      // tf32 bits: Wq|Wk|Wv|Wo|W1|W2

#define WT_WQ 0
#define WT_WK (1024 * 1024)
#define WT_WV (2 * 1024 * 1024)
#define WT_WO (3 * 1024 * 1024)
#define WT_W1 (4 * 1024 * 1024)
#define WT_W2 (8 * 1024 * 1024)

__device__ __forceinline__ uint32_t f2tf32(float x) {
    uint32_t y;
    asm("cvt.rna.tf32.f32 %0, %1;" : "=r"(y) : "f"(x));
    return y;
}

__device__ __forceinline__ void cp16(uint32_t dst_smem, const void* src) {
    asm volatile("cp.async.cg.shared.global [%0], [%1], 16;\n" ::
                 "r"(dst_smem), "l"(src));
}

__device__ __forceinline__ void mma_tf32(float& c0, float& c1, float& c2, float& c3,
                                         uint32_t a0, uint32_t a1, uint32_t a2, uint32_t a3,
                                         uint32_t b0, uint32_t b1) {
    asm volatile(
        "mma.sync.aligned.m16n8k8.row.col.f32.tf32.tf32.f32 "
        "{%0,%1,%2,%3}, {%4,%5,%6,%7}, {%8,%9}, {%0,%1,%2,%3};\n"
        : "+f"(c0), "+f"(c1), "+f"(c2), "+f"(c3)
        : "r"(a0), "r"(a1), "r"(a2), "r"(a3), "r"(b0), "r"(b1));
}

// ---------------------------------------------------------------------------
// Elementwise fp32 -> tf32-bits conversion (vectorized)
// ---------------------------------------------------------------------------
__global__ __launch_bounds__(256)
void cvt_tf32_kernel(const float4* __restrict__ in, uint4* __restrict__ out, int n4)
{
    const int i = blockIdx.x * blockDim.x + threadIdx.x;
    if (i < n4) {
        float4 v = in[i];
        uint4 o;
        o.x = f2tf32(v.x); o.y = f2tf32(v.y);
        o.z = f2tf32(v.z); o.w = f2tf32(v.w);
        out[i] = o;
    }
}

// ---------------------------------------------------------------------------
// TF32 tensor-core GEMM, pre-rounded operands. 128x128 block tile, BK=32.
// 128 threads = 4 warps in 2x2; warp tile 64x64 -> 1.0 LDS per MMA.
// ---------------------------------------------------------------------------
#define BM 128
#define BN 128
#define BK 32
#define ASTRIDE 36
#define BSTRIDE 132
#define ASZ (BM * ASTRIDE)
#define BSZ (BK * BSTRIDE)
#define SMEM_FLOATS (2 * (ASZ + BSZ))

template <bool RELU, bool BHSD, bool CVT_OUT>
__global__ __launch_bounds__(128)
void mma_gemm_kernel(const float* __restrict__ A, const float* __restrict__ W,
                     const float* __restrict__ bias, float* __restrict__ C,
                     int M, int N, int K)
{
    extern __shared__ float sm[];
    float* sA[2] = { sm, sm + ASZ };
    float* sB[2] = { sm + 2 * ASZ, sm + 2 * ASZ + BSZ };

    const int tid  = threadIdx.x;
    const int lane = tid & 31;
    const int warp = tid >> 5;
    const int wm   = warp >> 1;   // 0..1
    const int wn   = warp & 1;    // 0..1
    const int bm   = blockIdx.y * BM;
    const int bn   = blockIdx.x * BN;

    // global->smem mapping (128 threads)
    const int a_row = tid >> 3;          // 0..15 (+16/pass, 8 passes)
    const int a_col = (tid & 7) * 4;     // 0..28
    const int b_row = tid >> 5;          // 0..3 (+4/pass, 8 passes)
    const int b_col = (tid & 31) * 4;    // 0..124

    const float* Ag = A + (size_t)(bm + a_row) * K + a_col;
    const float* Bg = W + (size_t)b_row * N + bn + b_col;

    uint32_t sA_dst[2], sB_dst[2];
    sA_dst[0] = (uint32_t)__cvta_generic_to_shared(sA[0] + a_row * ASTRIDE + a_col);
    sA_dst[1] = (uint32_t)__cvta_generic_to_shared(sA[1] + a_row * ASTRIDE + a_col);
    sB_dst[0] = (uint32_t)__cvta_generic_to_shared(sB[0] + b_row * BSTRIDE + b_col);
    sB_dst[1] = (uint32_t)__cvta_generic_to_shared(sB[1] + b_row * BSTRIDE + b_col);

    const int nk = K / BK;

    {
#pragma unroll
        for (int p = 0; p < 8; p++)
            cp16(sA_dst[0] + p * 16 * ASTRIDE * 4, Ag + (size_t)p * 16 * K);
#pragma unroll
        for (int p = 0; p < 8; p++)
            cp16(sB_dst[0] + p * 4 * BSTRIDE * 4, Bg + (size_t)p * 4 * N);
        asm volatile("cp.async.commit_group;\n" ::);
    }

    float acc[4][8][4];
#pragma unroll
    for (int i = 0; i < 4; i++)
#pragma unroll
        for (int j = 0; j < 8; j++)
#pragma unroll
            for (int r = 0; r < 4; r++) acc[i][j][r] = 0.0f;

    const int lr = lane >> 2;
    const int lc = lane & 3;

    int buf = 0;
    for (int t = 0; t < nk; ++t) {
        asm volatile("cp.async.wait_group 0;\n" ::);
        __syncthreads();

        if (t + 1 < nk) {
            const float* Agn = Ag + (size_t)(t + 1) * BK;
            const float* Bgn = Bg + (size_t)(t + 1) * BK * N;
            const int nb = buf ^ 1;
#pragma unroll
            for (int p = 0; p < 8; p++)
                cp16(sA_dst[nb] + p * 16 * ASTRIDE * 4, Agn + (size_t)p * 16 * K);
#pragma unroll
            for (int p = 0; p < 8; p++)
                cp16(sB_dst[nb] + p * 4 * BSTRIDE * 4, Bgn + (size_t)p * 4 * N);
            asm volatile("cp.async.commit_group;\n" ::);
        }

        const uint32_t* __restrict__ Au = (const uint32_t*)sA[buf];
        const uint32_t* __restrict__ Bu = (const uint32_t*)sB[buf];

#pragma unroll
        for (int kk = 0; kk < 4; ++kk) {
            const int k0 = kk * 8 + lc;
            uint32_t af[4][4];
#pragma unroll
            for (int mt = 0; mt < 4; mt++) {
                const int r0 = wm * 64 + mt * 16 + lr;
                af[mt][0] = Au[r0 * ASTRIDE + k0];
                af[mt][1] = Au[(r0 + 8) * ASTRIDE + k0];
                af[mt][2] = Au[r0 * ASTRIDE + k0 + 4];
                af[mt][3] = Au[(r0 + 8) * ASTRIDE + k0 + 4];
            }
            uint32_t bf[8][2];
#pragma unroll
            for (int nt = 0; nt < 8; nt++) {
                const int c0 = wn * 64 + nt * 8 + lr;
                bf[nt][0] = Bu[(kk * 8 + lc) * BSTRIDE + c0];
                bf[nt][1] = Bu[(kk * 8 + 4 + lc) * BSTRIDE + c0];
            }
#pragma unroll
            for (int mt = 0; mt < 4; mt++)
#pragma unroll
                for (int nt = 0; nt < 8; nt++)
                    mma_tf32(acc[mt][nt][0], acc[mt][nt][1],
                             acc[mt][nt][2], acc[mt][nt][3],
                             af[mt][0], af[mt][1], af[mt][2], af[mt][3],
                             bf[nt][0], bf[nt][1]);
        }
        buf ^= 1;
    }

#pragma unroll
    for (int mt = 0; mt < 4; mt++) {
#pragma unroll
        for (int nt = 0; nt < 8; nt++) {
            const int col = bn + wn * 64 + nt * 8 + lc * 2;
            const float bv0 = bias[col];
            const float bv1 = bias[col + 1];
#pragma unroll
            for (int half = 0; half < 2; half++) {
                const int row = bm + wm * 64 + mt * 16 + lr + half * 8;
                float v0 = acc[mt][nt][half * 2 + 0] + bv0;
                float v1 = acc[mt][nt][half * 2 + 1] + bv1;
                if (RELU) { v0 = fmaxf(v0, 0.0f); v1 = fmaxf(v1, 0.0f); }
                if (CVT_OUT) {
                    v0 = __uint_as_float(f2tf32(v0));
                    v1 = __uint_as_float(f2tf32(v1));
                }
                float* dst;
                if (BHSD) {
                    const int b_ = row >> 11;
                    const int s_ = row & 2047;
                    const int h_ = col >> 6;
                    const int d_ = col & 63;
                    dst = C + ((size_t)(b_ * HH + h_) * SS + s_) * HDD + d_;
                } else {
                    dst = C + (size_t)row * N + col;
                }
                *(float2*)dst = make_float2(v0, v1);
            }
        }
    }
}

// ---------------------------------------------------------------------------
// Flash attention, TF32 mma (unchanged from R7 — known good)
// ---------------------------------------------------------------------------
#define KS_STRIDE 68
#define VS_STRIDE 72
#define PS_STRIDE 68
#define FLASH_SMEM_BYTES ((64 * KS_STRIDE + 64 * VS_STRIDE + 64 * PS_STRIDE) * 4)

__global__ __launch_bounds__(128)
void flash_mma_kernel(const float* __restrict__ Q, const float* __restrict__ Kg,
                      const float* __restrict__ Vg, float* __restrict__ Og)
{
    extern __shared__ float sm[];
    float* Ks = sm;
    float* Vs = Ks + 64 * KS_STRIDE;
    float* Ps = Vs + 64 * VS_STRIDE;

    const int tid  = threadIdx.x;
    const int warp = tid >> 5;
    const int lane = tid & 31;
    const int lr   = lane >> 2;
    const int lc   = lane & 3;
    const int bh   = blockIdx.y;
    const int q0   = blockIdx.x * 64;

    const float* qb = Q  + (size_t)bh * SS * HDD;
    const float* kb = Kg + (size_t)bh * SS * HDD;
    const float* vb = Vg + (size_t)bh * SS * HDD;

    uint32_t aq[8][4];
    {
        const int r0 = q0 + warp * 16 + lr;
#pragma unroll
        for (int kk = 0; kk < 8; kk++) {
            const int c = kk * 8 + lc;
            aq[kk][0] = __float_as_uint(qb[(size_t)r0 * HDD + c] * 0.125f);
            aq[kk][1] = __float_as_uint(qb[(size_t)(r0 + 8) * HDD + c] * 0.125f);
            aq[kk][2] = __float_as_uint(qb[(size_t)r0 * HDD + c + 4] * 0.125f);
            aq[kk][3] = __float_as_uint(qb[(size_t)(r0 + 8) * HDD + c + 4] * 0.125f);
        }
    }

    float o[8][4];
#pragma unroll
    for (int n = 0; n < 8; n++)
#pragma unroll
        for (int r = 0; r < 4; r++) o[n][r] = 0.0f;
    float m0 = -3.0e38f, m1 = -3.0e38f, l0 = 0.0f, l1 = 0.0f;

    float* Pw = Ps + warp * 16 * PS_STRIDE;

    for (int kt = 0; kt < SS / 64; ++kt) {
        __syncthreads();
        const float4* kp = (const float4*)(kb + (size_t)kt * 64 * HDD);
        const float4* vp = (const float4*)(vb + (size_t)kt * 64 * HDD);
#pragma unroll
        for (int p = 0; p < 8; p++) {
            const int idx = tid + p * 128;
            const int row = idx >> 4;
            const int c4  = (idx & 15) << 2;
            *(float4*)(Ks + row * KS_STRIDE + c4) = kp[idx];
            *(float4*)(Vs + row * VS_STRIDE + c4) = vp[idx];
        }
        __syncthreads();

        float s[8][4];
#pragma unroll
        for (int n = 0; n < 8; n++)
#pragma unroll
            for (int r = 0; r < 4; r++) s[n][r] = 0.0f;

        const uint32_t* Ku = (const uint32_t*)Ks;
#pragma unroll
        for (int kk = 0; kk < 8; kk++) {
            const int kc = kk * 8 + lc;
#pragma unroll
            for (int n = 0; n < 8; n++) {
                const uint32_t b0 = Ku[(n * 8 + lr) * KS_STRIDE + kc];
                const uint32_t b1 = Ku[(n * 8 + lr) * KS_STRIDE + kc + 4];
                mma_tf32(s[n][0], s[n][1], s[n][2], s[n][3],
                         aq[kk][0], aq[kk][1], aq[kk][2], aq[kk][3], b0, b1);
            }
        }

        float mx0 = -3.0e38f, mx1 = -3.0e38f;
#pragma unroll
        for (int n = 0; n < 8; n++) {
            mx0 = fmaxf(mx0, fmaxf(s[n][0], s[n][1]));
            mx1 = fmaxf(mx1, fmaxf(s[n][2], s[n][3]));
        }
        mx0 = fmaxf(mx0, __shfl_xor_sync(0xffffffffu, mx0, 1));
        mx0 = fmaxf(mx0, __shfl_xor_sync(0xffffffffu, mx0, 2));
        mx1 = fmaxf(mx1, __shfl_xor_sync(0xffffffffu, mx1, 1));
        mx1 = fmaxf(mx1, __shfl_xor_sync(0xffffffffu, mx1, 2));

        const float mn0 = fmaxf(m0, mx0);
        const float mn1 = fmaxf(m1, mx1);
        const float al0 = __expf(m0 - mn0);
        const float al1 = __expf(m1 - mn1);
        m0 = mn0; m1 = mn1;

        float rs0 = 0.0f, rs1 = 0.0f;
#pragma unroll
        for (int n = 0; n < 8; n++) {
            s[n][0] = __expf(s[n][0] - mn0);
            s[n][1] = __expf(s[n][1] - mn0);
            s[n][2] = __expf(s[n][2] - mn1);
            s[n][3] = __expf(s[n][3] - mn1);
            rs0 += s[n][0] + s[n][1];
            rs1 += s[n][2] + s[n][3];
        }
        rs0 += __shfl_xor_sync(0xffffffffu, rs0, 1);
        rs0 += __shfl_xor_sync(0xffffffffu, rs0, 2);
        rs1 += __shfl_xor_sync(0xffffffffu, rs1, 1);
        rs1 += __shfl_xor_sync(0xffffffffu, rs1, 2);
        l0 = l0 * al0 + rs0;
        l1 = l1 * al1 + rs1;

#pragma unroll
        for (int n = 0; n < 8; n++) {
            o[n][0] *= al0; o[n][1] *= al0;
            o[n][2] *= al1; o[n][3] *= al1;
        }

#pragma unroll
        for (int n = 0; n < 8; n++) {
            uint2 p01; p01.x = f2tf32(s[n][0]); p01.y = f2tf32(s[n][1]);
            *(uint2*)(Pw + lr * PS_STRIDE + n * 8 + 2 * lc) = p01;
            uint2 p23; p23.x = f2tf32(s[n][2]); p23.y = f2tf32(s[n][3]);
            *(uint2*)(Pw + (lr + 8) * PS_STRIDE + n * 8 + 2 * lc) = p23;
        }
        __syncwarp();

        const uint32_t* Pu = (const uint32_t*)Pw;
        const uint32_t* Vu = (const uint32_t*)Vs;
#pragma unroll
        for (int kk = 0; kk < 8; kk++) {
            const int kc = kk * 8 + lc;
            const uint32_t a0 = Pu[lr * PS_STRIDE + kc];
            const uint32_t a1 = Pu[(lr + 8) * PS_STRIDE + kc];
            const uint32_t a2 = Pu[lr * PS_STRIDE + kc + 4];
            const uint32_t a3 = Pu[(lr + 8) * PS_STRIDE + kc + 4];
#pragma unroll
            for (int n = 0; n < 8; n++) {
                const uint32_t b0 = Vu[kc * VS_STRIDE + n * 8 + lr];
                const uint32_t b1 = Vu[(kc + 4) * VS_STRIDE + n * 8 + lr];
                mma_tf32(o[n][0], o[n][1], o[n][2], o[n][3],
                         a0, a1, a2, a3, b0, b1);
            }
        }
        __syncwarp();
    }

    const float inv0 = 1.0f / l0;
    const float inv1 = 1.0f / l1;
    const int b_ = bh >> 4;
    const int h_ = bh & 15;
    const size_t row0 = (size_t)b_ * SS + q0 + warp * 16 + lr;
    float* d0 = Og + row0 * DD + h_ * HDD;
    float* d1 = Og + (row0 + 8) * DD + h_ * HDD;
#pragma unroll
    for (int n = 0; n < 8; n++) {
        *(float2*)(d0 + n * 8 + 2 * lc) =
            make_float2(__uint_as_float(f2tf32(o[n][0] * inv0)),
                        __uint_as_float(f2tf32(o[n][1] * inv0)));
        *(float2*)(d1 + n * 8 + 2 * lc) =
            make_float2(__uint_as_float(f2tf32(o[n][2] * inv1)),
                        __uint_as_float(f2tf32(o[n][3] * inv1)));
    }
}

// ---------------------------------------------------------------------------
// Fused residual + LayerNorm. WRITE_T additionally writes a tf32-bits copy.
// ---------------------------------------------------------------------------
template <bool WRITE_T>
__global__ __launch_bounds__(256)
void ln_kernel(const float* __restrict__ x1, const float* __restrict__ x2,
               const float* __restrict__ gamma, const float* __restrict__ beta,
               float* __restrict__ out, float* __restrict__ out_t)
{
    const int row = blockIdx.x;
    const int tid = threadIdx.x;
    const float4 a = ((const float4*)(x1 + (size_t)row * DD))[tid];
    const float4 b = ((const float4*)(x2 + (size_t)row * DD))[tid];
    float4 x = make_float4(a.x + b.x, a.y + b.y, a.z + b.z, a.w + b.w);

    float s = x.x + x.y + x.z + x.w;
    float q = x.x * x.x + x.y * x.y + x.z * x.z + x.w * x.w;

    __shared__ float shs[8], shq[8];
    const int lane = tid & 31, wid = tid >> 5;
#pragma unroll
    for (int o = 16; o; o >>= 1) {
        s += __shfl_xor_sync(0xffffffffu, s, o);
        q += __shfl_xor_sync(0xffffffffu, q, o);
    }
    if (lane == 0) { shs[wid] = s; shq[wid] = q; }
    __syncthreads();
    if (tid == 0) {
        float ts = 0.0f, tq = 0.0f;
#pragma unroll
        for (int i = 0; i < 8; i++) { ts += shs[i]; tq += shq[i]; }
        shs[0] = ts; shq[0] = tq;
    }
    __syncthreads();
    const float mean = shs[0] * (1.0f / DD);
    const float var  = shq[0] * (1.0f / DD) - mean * mean;
    const float rstd = rsqrtf(var + 1e-5f);

    const float4 g  = ((const float4*)gamma)[tid];
    const float4 be = ((const float4*)beta)[tid];
    float4 o;
    o.x = (x.x - mean) * rstd * g.x + be.x;
    o.y = (x.y - mean) * rstd * g.y + be.y;
    o.z = (x.z - mean) * rstd * g.z + be.z;
    o.w = (x.w - mean) * rstd * g.w + be.w;
    ((float4*)(out + (size_t)row * DD))[tid] = o;
    if (WRITE_T) {
        float4 ot;
        ot.x = __uint_as_float(f2tf32(o.x));
        ot.y = __uint_as_float(f2tf32(o.y));
        ot.z = __uint_as_float(f2tf32(o.z));
        ot.w = __uint_as_float(f2tf32(o.w));
        ((float4*)(out_t + (size_t)row * DD))[tid] = ot;
    }
}

// ---------------------------------------------------------------------------
// Launch
// ---------------------------------------------------------------------------
extern "C" void kernel_launch(void* const* d_in, const int* in_sizes, int n_in,
                              void* d_out, int out_size)
{
    const float* src = (const float*)d_in[0];
    const float* Wq  = (const float*)d_in[1];
    const float* bq  = (const float*)d_in[2];
    const float* Wk  = (const float*)d_in[3];
    const float* bk  = (const float*)d_in[4];
    const float* Wv  = (const float*)d_in[5];
    const float* bv  = (const float*)d_in[6];
    const float* Wo  = (const float*)d_in[7];
    const float* bo  = (const float*)d_in[8];
    const float* g1  = (const float*)d_in[9];
    const float* b1  = (const float*)d_in[10];
    const float* W1  = (const float*)d_in[11];
    const float* bf1 = (const float*)d_in[12];
    const float* W2  = (const float*)d_in[13];
    const float* bf2 = (const float*)d_in[14];
    const float* g2  = (const float*)d_in[15];
    const float* b2  = (const float*)d_in[16];
    float* out = (float*)d_out;

    float *qp, *kp, *vp, *attnp, *tmpp, *src1p, *src1tp, *srctp, *ff1p, *wtp;
    cudaGetSymbolAddress((void**)&qp,     g_q);
    cudaGetSymbolAddress((void**)&kp,     g_k);
    cudaGetSymbolAddress((void**)&vp,     g_v);
    cudaGetSymbolAddress((void**)&attnp,  g_attn);
    cudaGetSymbolAddress((void**)&tmpp,   g_tmp);
    cudaGetSymbolAddress((void**)&src1p,  g_src1);
    cudaGetSymbolAddress((void**)&src1tp, g_src1_t);
    cudaGetSymbolAddress((void**)&srctp,  g_src_t);
    cudaGetSymbolAddress((void**)&ff1p,   g_ff1);
    cudaGetSymbolAddress((void**)&wtp,    g_wt);

    const int GEMM_SMEM = SMEM_FLOATS * 4;   // 70656 B

    cudaFuncSetAttribute(mma_gemm_kernel<false, true,  true>,
                         cudaFuncAttributeMaxDynamicSharedMemorySize, GEMM_SMEM);
    cudaFuncSetAttribute(mma_gemm_kernel<false, false, false>,
                         cudaFuncAttributeMaxDynamicSharedMemorySize, GEMM_SMEM);
    cudaFuncSetAttribute(mma_gemm_kernel<true,  false, true>,
                         cudaFuncAttributeMaxDynamicSharedMemorySize, GEMM_SMEM);
    cudaFuncSetAttribute(flash_mma_kernel,
                         cudaFuncAttributeMaxDynamicSharedMemorySize, FLASH_SMEM_BYTES);

    // Pre-round everything static to tf32 bits (src + 6 weight matrices)
    {
        const int T = 256;
        cvt_tf32_kernel<<<(NR * DD / 4 + T - 1) / T, T>>>(
            (const float4*)src, (uint4*)srctp, NR * DD / 4);
        cvt_tf32_kernel<<<(DD * DD / 4 + T - 1) / T, T>>>(
            (const float4*)Wq, (uint4*)(wtp + WT_WQ), DD * DD / 4);
        cvt_tf32_kernel<<<(DD * DD / 4 + T - 1) / T, T>>>(
            (const float4*)Wk, (uint4*)(wtp + WT_WK), DD * DD / 4);
        cvt_tf32_kernel<<<(DD * DD / 4 + T - 1) / T, T>>>(
            (const float4*)Wv, (uint4*)(wtp + WT_WV), DD * DD / 4);
        cvt_tf32_kernel<<<(DD * DD / 4 + T - 1) / T, T>>>(
            (const float4*)Wo, (uint4*)(wtp + WT_WO), DD * DD / 4);
        cvt_tf32_kernel<<<(DD * PFF / 4 + T - 1) / T, T>>>(
            (const float4*)W1, (uint4*)(wtp + WT_W1), DD * PFF / 4);
        cvt_tf32_kernel<<<(PFF * DD / 4 + T - 1) / T, T>>>(
            (const float4*)W2, (uint4*)(wtp + WT_W2), PFF * DD / 4);
    }

    dim3 gblk(128);
    dim3 gD(DD / BN, NR / BM);     // (8, 64)
    dim3 gPF(PFF / BN, NR / BM);   // (32, 64)
    dim3 gF(SS / 64, BB * HH);     // (32, 64)

    // QKV projections -> [B,H,S,HD], outputs tf32 bits
    mma_gemm_kernel<false, true, true><<<gD, gblk, GEMM_SMEM>>>(
        srctp, wtp + WT_WQ, bq, qp, NR, DD, DD);
    mma_gemm_kernel<false, true, true><<<gD, gblk, GEMM_SMEM>>>(
        srctp, wtp + WT_WK, bk, kp, NR, DD, DD);
    mma_gemm_kernel<false, true, true><<<gD, gblk, GEMM_SMEM>>>(
        srctp, wtp + WT_WV, bv, vp, NR, DD, DD);
    // attention (tensor-core flash), outputs tf32 bits
    flash_mma_kernel<<<gF, dim3(128), FLASH_SMEM_BYTES>>>(qp, kp, vp, attnp);
    // O projection, outputs fp32
    mma_gemm_kernel<false, false, false><<<gD, gblk, GEMM_SMEM>>>(
        attnp, wtp + WT_WO, bo, tmpp, NR, DD, DD);
    // residual + LN 1 -> fp32 + tf32 copies
    ln_kernel<true><<<NR, dim3(256)>>>(src, tmpp, g1, b1, src1p, src1tp);
    // FFN1 (ReLU), outputs tf32 bits
    mma_gemm_kernel<true, false, true><<<gPF, gblk, GEMM_SMEM>>>(
        src1tp, wtp + WT_W1, bf1, ff1p, NR, PFF, DD);
    // FFN2, outputs fp32
    mma_gemm_kernel<false, false, false><<<gD, gblk, GEMM_SMEM>>>(
        ff1p, wtp + WT_W2, bf2, tmpp, NR, DD, PFF);
    // residual + LN 2 -> output
    ln_kernel<false><<<NR, dim3(256)>>>(src1p, tmpp, g2, b2, out, nullptr);
}